// round 2
// baseline (speedup 1.0000x reference)
#include <cuda_runtime.h>
#include <math.h>

#define Bb 8
#define Ss 2048
#define Ee 512
#define Hh 8
#define Dd 64

// Scratch (device globals — no allocations allowed)
__device__ float g_Q [Bb*Hh*Ss*Dd];   // [b,h,s,d]
__device__ float g_Kt[Bb*Hh*Dd*Ss];   // [b,h,d,s]  (K pre-transposed)
__device__ float g_V [Bb*Hh*Ss*Dd];   // [b,h,s,d]
__device__ float g_att[Bb*Ss*Ee];     // [b*s, h*d] attention output (pre-projection)

// ---------------------------------------------------------------------------
// Fused QKV projection GEMM: C[m,n] = sum_k x[m,k] * W[h,k,d], n = h*64+d
// M = B*S = 16384, N = 512, K = 512. blockIdx.z selects Q/K/V.
// 128x128 tile, BK=8, 256 threads, 8x8 per-thread register tile.
// ---------------------------------------------------------------------------
__global__ __launch_bounds__(256) void gemm_qkv_kernel(
    const float* __restrict__ x,
    const float* __restrict__ Wq,
    const float* __restrict__ Wk,
    const float* __restrict__ Wv)
{
    const int proj = blockIdx.z;
    const float* __restrict__ W = (proj == 0) ? Wq : ((proj == 1) ? Wk : Wv);
    const int m0 = blockIdx.x * 128;
    const int n0 = blockIdx.y * 128;

    __shared__ float As[8][128];   // A transposed: As[k][m]
    __shared__ float Bs[8][128];   // Bs[k][n]

    const int tid = threadIdx.x;
    const int tx = tid & 15;
    const int ty = tid >> 4;

    float acc[8][8];
#pragma unroll
    for (int i = 0; i < 8; i++)
#pragma unroll
        for (int j = 0; j < 8; j++) acc[i][j] = 0.0f;

    for (int k0 = 0; k0 < Ee; k0 += 8) {
        // Load A tile (128 rows x 8 k) — one float4 per thread, store transposed
        {
            const int am = tid >> 1;
            const int ac = (tid & 1) * 4;
            float4 av = *(const float4*)(x + (m0 + am) * Ee + k0 + ac);
            As[ac + 0][am] = av.x;
            As[ac + 1][am] = av.y;
            As[ac + 2][am] = av.z;
            As[ac + 3][am] = av.w;
        }
        // Load B tile (8 k x 128 n) — one float4 per thread
        {
            const int bk = tid >> 5;
            const int bn = (tid & 31) * 4;
            const int n = n0 + bn;
            const int h = n >> 6;
            const int d = n & 63;
            *(float4*)&Bs[bk][bn] =
                *(const float4*)(W + h * (Ee * Dd) + (k0 + bk) * Dd + d);
        }
        __syncthreads();

#pragma unroll
        for (int kk = 0; kk < 8; kk++) {
            float a[8], bb[8];
            *(float4*)(a)     = *(const float4*)&As[kk][ty * 8];
            *(float4*)(a + 4) = *(const float4*)&As[kk][ty * 8 + 4];
            *(float4*)(bb)     = *(const float4*)&Bs[kk][tx * 8];
            *(float4*)(bb + 4) = *(const float4*)&Bs[kk][tx * 8 + 4];
#pragma unroll
            for (int i = 0; i < 8; i++)
#pragma unroll
                for (int j = 0; j < 8; j++) acc[i][j] += a[i] * bb[j];
        }
        __syncthreads();
    }

    // Epilogue: scatter into attention layouts
#pragma unroll
    for (int i = 0; i < 8; i++) {
        const int m = m0 + ty * 8 + i;
        const int b = m >> 11;        // / 2048
        const int s = m & 2047;
#pragma unroll
        for (int j = 0; j < 8; j++) {
            const int n = n0 + tx * 8 + j;
            const int h = n >> 6;
            const int d = n & 63;
            const float v = acc[i][j];
            if (proj == 0)      g_Q [((b * Hh + h) * Ss + s) * Dd + d] = v;
            else if (proj == 2) g_V [((b * Hh + h) * Ss + s) * Dd + d] = v;
            else                g_Kt[((b * Hh + h) * Dd + d) * Ss + s] = v;
        }
    }
}

// ---------------------------------------------------------------------------
// Flash attention: one CTA per (b, h, 64-row query tile). Causal, online
// softmax. 64x64 K/V tiles. 256 threads (16x16), thread owns rows ty*4..+3
// and strided columns jj*16+tx.
// Shared: Qs[64][68], KPs[64][68] (K tile, later aliased as P), Vs[64][68].
// ---------------------------------------------------------------------------
#define ATTN_SMEM (3 * 64 * 68 * 4)

__global__ __launch_bounds__(256) void attn_kernel()
{
    extern __shared__ float sm[];
    float* Qs  = sm;                 // [r][d] stride 68
    float* KPs = sm + 64 * 68;       // [d][c] for K tile; [r][c] for P
    float* Vs  = sm + 2 * 64 * 68;   // [c][d] stride 68

    const int qt = blockIdx.x;
    const int h  = blockIdx.y;
    const int b  = blockIdx.z;
    const int tid = threadIdx.x;
    const int tx = tid & 15;
    const int ty = tid >> 4;

    const float* __restrict__ Qg  = g_Q  + ((b * Hh + h) * Ss + qt * 64) * Dd;
    const float* __restrict__ Ktg = g_Kt + (b * Hh + h) * Dd * Ss;
    const float* __restrict__ Vg  = g_V  + (b * Hh + h) * Ss * Dd;

    // Load Q tile (scale folded in: 1/sqrt(64) = 0.125)
#pragma unroll
    for (int l = 0; l < 4; l++) {
        const int i = tid + l * 256;
        const int r = i >> 4;
        const int c = (i & 15) * 4;
        float4 v = *(const float4*)(Qg + r * Dd + c);
        v.x *= 0.125f; v.y *= 0.125f; v.z *= 0.125f; v.w *= 0.125f;
        *(float4*)&Qs[r * 68 + c] = v;
    }

    float m_run[4] = {-1e30f, -1e30f, -1e30f, -1e30f};
    float l_run[4] = {0.0f, 0.0f, 0.0f, 0.0f};
    float acc[4][4];
#pragma unroll
    for (int i = 0; i < 4; i++)
#pragma unroll
        for (int jj = 0; jj < 4; jj++) acc[i][jj] = 0.0f;

    for (int j = 0; j <= qt; j++) {
        __syncthreads();   // previous-iteration P/V reads done (and Q load on iter 0)
        // Load K tile [d][c] (direct copy — K already transposed in global)
        // and V tile [c][d]
#pragma unroll
        for (int l = 0; l < 4; l++) {
            const int i = tid + l * 256;
            const int r = i >> 4;
            const int c = (i & 15) * 4;
            *(float4*)&KPs[r * 68 + c] = *(const float4*)(Ktg + r * Ss + j * 64 + c);
            *(float4*)&Vs [r * 68 + c] = *(const float4*)(Vg + (j * 64 + r) * Dd + c);
        }
        __syncthreads();

        // S = Q K^T tile (scores)
        float s[4][4];
#pragma unroll
        for (int i = 0; i < 4; i++)
#pragma unroll
            for (int jj = 0; jj < 4; jj++) s[i][jj] = 0.0f;

#pragma unroll
        for (int d4 = 0; d4 < 64; d4 += 4) {
            float qa[4][4];
#pragma unroll
            for (int i = 0; i < 4; i++)
                *(float4*)qa[i] = *(const float4*)&Qs[(ty * 4 + i) * 68 + d4];
#pragma unroll
            for (int dd = 0; dd < 4; dd++) {
                float kv[4];
#pragma unroll
                for (int jj = 0; jj < 4; jj++)
                    kv[jj] = KPs[(d4 + dd) * 68 + jj * 16 + tx];
#pragma unroll
                for (int i = 0; i < 4; i++)
#pragma unroll
                    for (int jj = 0; jj < 4; jj++)
                        s[i][jj] += qa[i][dd] * kv[jj];
            }
        }

        // Causal mask on the diagonal tile
        if (j == qt) {
#pragma unroll
            for (int i = 0; i < 4; i++)
#pragma unroll
                for (int jj = 0; jj < 4; jj++)
                    if (jj * 16 + tx > ty * 4 + i) s[i][jj] = -1e30f;
        }

        // Online softmax update
        float alpha[4];
#pragma unroll
        for (int i = 0; i < 4; i++) {
            float tm = fmaxf(fmaxf(s[i][0], s[i][1]), fmaxf(s[i][2], s[i][3]));
#pragma unroll
            for (int off = 8; off > 0; off >>= 1)
                tm = fmaxf(tm, __shfl_xor_sync(0xffffffffu, tm, off));
            const float mn = fmaxf(m_run[i], tm);
            alpha[i] = __expf(m_run[i] - mn);
            m_run[i] = mn;
            float rs = 0.0f;
#pragma unroll
            for (int jj = 0; jj < 4; jj++) {
                s[i][jj] = __expf(s[i][jj] - mn);
                rs += s[i][jj];
            }
#pragma unroll
            for (int off = 8; off > 0; off >>= 1)
                rs += __shfl_xor_sync(0xffffffffu, rs, off);
            l_run[i] = l_run[i] * alpha[i] + rs;
#pragma unroll
            for (int jj = 0; jj < 4; jj++) acc[i][jj] *= alpha[i];
        }

        __syncthreads();   // done reading K tile
        // Stage P into the K-tile buffer: KPs[r][c]
#pragma unroll
        for (int i = 0; i < 4; i++)
#pragma unroll
            for (int jj = 0; jj < 4; jj++)
                KPs[(ty * 4 + i) * 68 + jj * 16 + tx] = s[i][jj];
        __syncthreads();

        // O += P @ V
#pragma unroll
        for (int c4 = 0; c4 < 64; c4 += 4) {
            float pa[4][4];
#pragma unroll
            for (int i = 0; i < 4; i++)
                *(float4*)pa[i] = *(const float4*)&KPs[(ty * 4 + i) * 68 + c4];
#pragma unroll
            for (int cc = 0; cc < 4; cc++) {
                float vv[4];
#pragma unroll
                for (int jj = 0; jj < 4; jj++)
                    vv[jj] = Vs[(c4 + cc) * 68 + jj * 16 + tx];
#pragma unroll
                for (int i = 0; i < 4; i++)
#pragma unroll
                    for (int jj = 0; jj < 4; jj++)
                        acc[i][jj] += pa[i][cc] * vv[jj];
            }
        }
    }

    // Epilogue: normalize and write to [b*s, h*64+d] layout
#pragma unroll
    for (int i = 0; i < 4; i++) {
        const float inv = 1.0f / l_run[i];
        const int row = b * Ss + qt * 64 + ty * 4 + i;
#pragma unroll
        for (int jj = 0; jj < 4; jj++)
            g_att[row * Ee + h * 64 + jj * 16 + tx] = acc[i][jj] * inv;
    }
}

// ---------------------------------------------------------------------------
// Output projection: out = g_att @ Wp + bp.  M=16384, N=512, K=512.
// Same 128x128x8 SGEMM structure.
// ---------------------------------------------------------------------------
__global__ __launch_bounds__(256) void gemm_proj_kernel(
    const float* __restrict__ Wp,
    const float* __restrict__ bp,
    float* __restrict__ out)
{
    const int m0 = blockIdx.x * 128;
    const int n0 = blockIdx.y * 128;

    __shared__ float As[8][128];
    __shared__ float Bs[8][128];

    const int tid = threadIdx.x;
    const int tx = tid & 15;
    const int ty = tid >> 4;

    float acc[8][8];
#pragma unroll
    for (int i = 0; i < 8; i++)
#pragma unroll
        for (int j = 0; j < 8; j++) acc[i][j] = 0.0f;

    for (int k0 = 0; k0 < Ee; k0 += 8) {
        {
            const int am = tid >> 1;
            const int ac = (tid & 1) * 4;
            float4 av = *(const float4*)(g_att + (m0 + am) * Ee + k0 + ac);
            As[ac + 0][am] = av.x;
            As[ac + 1][am] = av.y;
            As[ac + 2][am] = av.z;
            As[ac + 3][am] = av.w;
        }
        {
            const int bk = tid >> 5;
            const int bn = (tid & 31) * 4;
            *(float4*)&Bs[bk][bn] =
                *(const float4*)(Wp + (k0 + bk) * Ee + n0 + bn);
        }
        __syncthreads();

#pragma unroll
        for (int kk = 0; kk < 8; kk++) {
            float a[8], bb[8];
            *(float4*)(a)     = *(const float4*)&As[kk][ty * 8];
            *(float4*)(a + 4) = *(const float4*)&As[kk][ty * 8 + 4];
            *(float4*)(bb)     = *(const float4*)&Bs[kk][tx * 8];
            *(float4*)(bb + 4) = *(const float4*)&Bs[kk][tx * 8 + 4];
#pragma unroll
            for (int i = 0; i < 8; i++)
#pragma unroll
                for (int j = 0; j < 8; j++) acc[i][j] += a[i] * bb[j];
        }
        __syncthreads();
    }

    // Epilogue with bias, float4 stores
#pragma unroll
    for (int i = 0; i < 8; i++) {
        const int m = m0 + ty * 8 + i;
#pragma unroll
        for (int j = 0; j < 8; j += 4) {
            const int n = n0 + tx * 8 + j;
            float4 bv = *(const float4*)(bp + n);
            float4 ov;
            ov.x = acc[i][j + 0] + bv.x;
            ov.y = acc[i][j + 1] + bv.y;
            ov.z = acc[i][j + 2] + bv.z;
            ov.w = acc[i][j + 3] + bv.w;
            *(float4*)(out + (size_t)m * Ee + n) = ov;
        }
    }
}

// ---------------------------------------------------------------------------
extern "C" void kernel_launch(void* const* d_in, const int* in_sizes, int n_in,
                              void* d_out, int out_size)
{
    (void)in_sizes; (void)n_in; (void)out_size;
    const float* x  = (const float*)d_in[0];
    const float* Wq = (const float*)d_in[1];
    const float* Wk = (const float*)d_in[2];
    const float* Wv = (const float*)d_in[3];
    const float* Wp = (const float*)d_in[4];
    const float* bp = (const float*)d_in[5];
    float* out = (float*)d_out;

    cudaFuncSetAttribute(attn_kernel,
                         cudaFuncAttributeMaxDynamicSharedMemorySize, ATTN_SMEM);

    gemm_qkv_kernel<<<dim3(128, 4, 3), 256>>>(x, Wq, Wk, Wv);
    attn_kernel<<<dim3(Ss / 64, Hh, Bb), 256, ATTN_SMEM>>>();
    gemm_proj_kernel<<<dim3(128, 4), 256>>>(Wp, bp, out);
}

// round 6
// speedup vs baseline: 1.5495x; 1.5495x over previous
#include <cuda_runtime.h>
#include <math.h>
#include <cstdint>

#define Bb 8
#define Ss 2048
#define Ee 512
#define Hh 8
#define Dd 64

// Scratch (device globals — no allocations allowed)
__device__ float g_Q [Bb*Hh*Ss*Dd];   // [b,h,s,d]
__device__ float g_Kt[Bb*Hh*Dd*Ss];   // [b,h,d,s]  (K pre-transposed)
__device__ float g_V [Bb*Hh*Ss*Dd];   // [b,h,s,d]
__device__ float g_att[Bb*Ss*Ee];     // [b*s, h*d] attention output
__device__ float g_Wt[4*Ee*Ee];       // [proj][n][k] transposed weights (tf32-rounded)

// ---------------------------------------------------------------------------
__device__ __forceinline__ uint32_t smem_u32(const void* p) {
    uint32_t a;
    asm("{ .reg .u64 t; cvta.to.shared.u64 t, %1; cvt.u32.u64 %0, t; }" : "=r"(a) : "l"(p));
    return a;
}
#define CP_ASYNC16(dst_u32, src_ptr) \
    asm volatile("cp.async.cg.shared.global [%0], [%1], 16;" \
        :: "r"(dst_u32), "l"(__cvta_generic_to_global(src_ptr)) : "memory")
#define CP_COMMIT() asm volatile("cp.async.commit_group;" ::: "memory")
#define CP_WAIT_1() asm volatile("cp.async.wait_group 1;" ::: "memory")

#define MMA_TF32(c, a, b) \
    asm volatile("mma.sync.aligned.m16n8k8.row.col.f32.tf32.tf32.f32 " \
        "{%0,%1,%2,%3}, {%4,%5,%6,%7}, {%8,%9}, {%0,%1,%2,%3};" \
        : "+f"((c)[0]), "+f"((c)[1]), "+f"((c)[2]), "+f"((c)[3]) \
        : "r"((a)[0]), "r"((a)[1]), "r"((a)[2]), "r"((a)[3]), \
          "r"((b)[0]), "r"((b)[1]))

__device__ __forceinline__ uint32_t f2tf32(float f) {
    uint32_t u;
    asm("cvt.rna.tf32.f32 %0, %1;" : "=r"(u) : "f"(f));
    return u;
}

// ---------------------------------------------------------------------------
// Weight transpose + tf32 round: g_Wt[p][n][k]
//   p<3:  W[h][k][d], n = h*64+d   p==3: Wp[k][n]
// ---------------------------------------------------------------------------
__global__ __launch_bounds__(1024) void transpose_w_kernel(
    const float* __restrict__ Wq, const float* __restrict__ Wk,
    const float* __restrict__ Wv, const float* __restrict__ Wp)
{
    const int idx = blockIdx.x * 1024 + threadIdx.x;   // 4*512*512 = 1M threads
    const int p = idx >> 18;
    const int r = idx & 262143;
    const int n = r >> 9;
    const int k = r & 511;
    const float* __restrict__ W = (p == 0) ? Wq : (p == 1) ? Wk : (p == 2) ? Wv : Wp;
    float v;
    if (p < 3) {
        const int h = n >> 6, d = n & 63;
        v = W[(h * Ee + k) * Dd + d];
    } else {
        v = W[k * Ee + n];
    }
    g_Wt[idx] = __uint_as_float(f2tf32(v));
}

// ---------------------------------------------------------------------------
// tf32 mma.sync GEMM: C[16384 x 512] = A[16384 x 512] * Wt^T  (Wt is [n][k]).
// CTA 128x128, BK=32, 2-stage cp.async. 8 warps (4M x 2N), warp tile 32x64.
// SMEM tiles [row][k] with 16B-chunk swizzle: chunk' = chunk ^ (row & 7).
// mode: 0=Q scatter, 1=K^T scatter, 2=V scatter, 3=proj (+bias -> out).
// ---------------------------------------------------------------------------
#define STAGE_F (128*32 + 128*32)           // floats per stage (A + B)
#define GEMM_SMEM (2 * STAGE_F * 4)         // 65536 bytes

__global__ __launch_bounds__(256) void gemm_mma_kernel(
    const float* __restrict__ Aglob, int mode_in,
    const float* __restrict__ bp, float* __restrict__ out)
{
    extern __shared__ float sm[];
    const int tid = threadIdx.x;
    const int wid = tid >> 5;
    const int lane = tid & 31;
    const int g = lane >> 2;        // 0..7
    const int t = lane & 3;         // 0..3
    const int wm = wid & 3;         // warp M position (4)
    const int wn = wid >> 2;        // warp N position (2)

    const int mode = (mode_in < 0) ? (int)blockIdx.z : mode_in;
    const float* __restrict__ Ag = (mode == 3) ? g_att : Aglob;
    const float* __restrict__ Bg = g_Wt + (size_t)mode * (Ee * Ee);
    const int m0 = blockIdx.x * 128;
    const int n0 = blockIdx.y * 128;

    const uint32_t smb = smem_u32(sm);

    float c[2][8][4];
#pragma unroll
    for (int i = 0; i < 2; i++)
#pragma unroll
        for (int j = 0; j < 8; j++)
#pragma unroll
            for (int q = 0; q < 4; q++) c[i][j][q] = 0.0f;

    // stage loader: A 128x32 + B 128x32, 16B chunks, swizzled
    auto load_stage = [&](int kt) {
        const uint32_t base = smb + (uint32_t)(kt & 1) * (STAGE_F * 4);
        const int k0 = kt * 32;
#pragma unroll
        for (int p = 0; p < 4; p++) {            // A: 1024 chunks
            const int id = tid + p * 256;
            const int row = id >> 3, ch = id & 7;
            CP_ASYNC16(base + (uint32_t)(row * 128 + ((ch ^ (row & 7)) * 16)),
                       Ag + (size_t)(m0 + row) * Ee + k0 + ch * 4);
        }
        const uint32_t bbase = base + 128 * 32 * 4;
#pragma unroll
        for (int p = 0; p < 4; p++) {            // B: 1024 chunks
            const int id = tid + p * 256;
            const int row = id >> 3, ch = id & 7;
            CP_ASYNC16(bbase + (uint32_t)(row * 128 + ((ch ^ (row & 7)) * 16)),
                       Bg + (size_t)(n0 + row) * Ee + k0 + ch * 4);
        }
    };

    load_stage(0);
    CP_COMMIT();

    const int NT = Ee / 32;   // 16
    for (int kt = 0; kt < NT; kt++) {
        if (kt + 1 < NT) load_stage(kt + 1);
        CP_COMMIT();
        CP_WAIT_1();
        __syncthreads();

        const float* As = sm + (kt & 1) * STAGE_F;
        const float* Bs = As + 128 * 32;

#pragma unroll
        for (int ks = 0; ks < 4; ks++) {
            const int ch0 = (2 * ks) ^ g;        // swizzled chunk for k = ks*8 + t
            const int ch1 = (2 * ks + 1) ^ g;    // swizzled chunk for k = ks*8 + 4 + t

            uint32_t a[2][4];
#pragma unroll
            for (int i = 0; i < 2; i++) {
                const int row = wm * 32 + i * 16 + g;
                a[i][0] = f2tf32(As[row * 32 + ch0 * 4 + t]);
                a[i][1] = f2tf32(As[(row + 8) * 32 + ch0 * 4 + t]);
                a[i][2] = f2tf32(As[row * 32 + ch1 * 4 + t]);
                a[i][3] = f2tf32(As[(row + 8) * 32 + ch1 * 4 + t]);
            }
            uint32_t b[8][2];
#pragma unroll
            for (int j = 0; j < 8; j++) {
                const int rn = wn * 64 + j * 8 + g;
                b[j][0] = __float_as_uint(Bs[rn * 32 + ch0 * 4 + t]);
                b[j][1] = __float_as_uint(Bs[rn * 32 + ch1 * 4 + t]);
            }
#pragma unroll
            for (int i = 0; i < 2; i++)
#pragma unroll
                for (int j = 0; j < 8; j++)
                    MMA_TF32(c[i][j], a[i], b[j]);
        }
        __syncthreads();
    }

    // Epilogue. Fragment (i,j): rows m0+wm*32+i*16+g (+8), cols n0+wn*64+j*8+2t (+1)
#pragma unroll
    for (int i = 0; i < 2; i++) {
        const int mrow = m0 + wm * 32 + i * 16 + g;
#pragma unroll
        for (int rr = 0; rr < 2; rr++) {
            const int m = mrow + rr * 8;
            const int b_ = m >> 11;
            const int s = m & 2047;
#pragma unroll
            for (int j = 0; j < 8; j++) {
                const int n = n0 + wn * 64 + j * 8 + 2 * t;
                const float v0 = c[i][j][rr * 2 + 0];
                const float v1 = c[i][j][rr * 2 + 1];
                if (mode == 0 || mode == 2) {
                    const int h = n >> 6, d = n & 63;
                    float* dst = ((mode == 0) ? g_Q : g_V)
                               + (((size_t)(b_ * Hh + h) * Ss + s) * Dd + d);
                    *(float2*)dst = make_float2(v0, v1);
                } else if (mode == 1) {
                    const int h = n >> 6, d = n & 63;
                    float* dst = g_Kt + ((size_t)(b_ * Hh + h) * Dd + d) * Ss + s;
                    dst[0] = v0;
                    dst[Ss] = v1;   // d+1 row
                } else {
                    float* dst = out + (size_t)m * Ee + n;
                    *(float2*)dst = make_float2(v0 + bp[n], v1 + bp[n + 1]);
                }
            }
        }
    }
}

// ---------------------------------------------------------------------------
// Flash attention (unchanged, known good): one CTA per (b, h, 64-row query
// tile), causal, online softmax, 64x64 K/V tiles, fp32 SIMT.
// ---------------------------------------------------------------------------
#define ATTN_SMEM (3 * 64 * 68 * 4)

__global__ __launch_bounds__(256) void attn_kernel()
{
    extern __shared__ float smf[];
    float* Qs  = smf;
    float* KPs = smf + 64 * 68;
    float* Vs  = smf + 2 * 64 * 68;

    const int qt = blockIdx.x;
    const int h  = blockIdx.y;
    const int b  = blockIdx.z;
    const int tid = threadIdx.x;
    const int tx = tid & 15;
    const int ty = tid >> 4;

    const float* __restrict__ Qg  = g_Q  + ((b * Hh + h) * Ss + qt * 64) * Dd;
    const float* __restrict__ Ktg = g_Kt + (b * Hh + h) * Dd * Ss;
    const float* __restrict__ Vg  = g_V  + (b * Hh + h) * Ss * Dd;

#pragma unroll
    for (int l = 0; l < 4; l++) {
        const int i = tid + l * 256;
        const int r = i >> 4;
        const int cc = (i & 15) * 4;
        float4 v = *(const float4*)(Qg + r * Dd + cc);
        v.x *= 0.125f; v.y *= 0.125f; v.z *= 0.125f; v.w *= 0.125f;
        *(float4*)&Qs[r * 68 + cc] = v;
    }

    float m_run[4] = {-1e30f, -1e30f, -1e30f, -1e30f};
    float l_run[4] = {0.0f, 0.0f, 0.0f, 0.0f};
    float acc[4][4];
#pragma unroll
    for (int i = 0; i < 4; i++)
#pragma unroll
        for (int jj = 0; jj < 4; jj++) acc[i][jj] = 0.0f;

    for (int j = 0; j <= qt; j++) {
        __syncthreads();
#pragma unroll
        for (int l = 0; l < 4; l++) {
            const int i = tid + l * 256;
            const int r = i >> 4;
            const int cc = (i & 15) * 4;
            *(float4*)&KPs[r * 68 + cc] = *(const float4*)(Ktg + r * Ss + j * 64 + cc);
            *(float4*)&Vs [r * 68 + cc] = *(const float4*)(Vg + (j * 64 + r) * Dd + cc);
        }
        __syncthreads();

        float s[4][4];
#pragma unroll
        for (int i = 0; i < 4; i++)
#pragma unroll
            for (int jj = 0; jj < 4; jj++) s[i][jj] = 0.0f;

#pragma unroll
        for (int d4 = 0; d4 < 64; d4 += 4) {
            float qa[4][4];
#pragma unroll
            for (int i = 0; i < 4; i++)
                *(float4*)qa[i] = *(const float4*)&Qs[(ty * 4 + i) * 68 + d4];
#pragma unroll
            for (int dd = 0; dd < 4; dd++) {
                float kv[4];
#pragma unroll
                for (int jj = 0; jj < 4; jj++)
                    kv[jj] = KPs[(d4 + dd) * 68 + jj * 16 + tx];
#pragma unroll
                for (int i = 0; i < 4; i++)
#pragma unroll
                    for (int jj = 0; jj < 4; jj++)
                        s[i][jj] += qa[i][dd] * kv[jj];
            }
        }

        if (j == qt) {
#pragma unroll
            for (int i = 0; i < 4; i++)
#pragma unroll
                for (int jj = 0; jj < 4; jj++)
                    if (jj * 16 + tx > ty * 4 + i) s[i][jj] = -1e30f;
        }

        float alpha[4];
#pragma unroll
        for (int i = 0; i < 4; i++) {
            float tm = fmaxf(fmaxf(s[i][0], s[i][1]), fmaxf(s[i][2], s[i][3]));
#pragma unroll
            for (int off = 8; off > 0; off >>= 1)
                tm = fmaxf(tm, __shfl_xor_sync(0xffffffffu, tm, off));
            const float mn = fmaxf(m_run[i], tm);
            alpha[i] = __expf(m_run[i] - mn);
            m_run[i] = mn;
            float rs = 0.0f;
#pragma unroll
            for (int jj = 0; jj < 4; jj++) {
                s[i][jj] = __expf(s[i][jj] - mn);
                rs += s[i][jj];
            }
#pragma unroll
            for (int off = 8; off > 0; off >>= 1)
                rs += __shfl_xor_sync(0xffffffffu, rs, off);
            l_run[i] = l_run[i] * alpha[i] + rs;
#pragma unroll
            for (int jj = 0; jj < 4; jj++) acc[i][jj] *= alpha[i];
        }

        __syncthreads();
#pragma unroll
        for (int i = 0; i < 4; i++)
#pragma unroll
            for (int jj = 0; jj < 4; jj++)
                KPs[(ty * 4 + i) * 68 + jj * 16 + tx] = s[i][jj];
        __syncthreads();

#pragma unroll
        for (int c4 = 0; c4 < 64; c4 += 4) {
            float pa[4][4];
#pragma unroll
            for (int i = 0; i < 4; i++)
                *(float4*)pa[i] = *(const float4*)&KPs[(ty * 4 + i) * 68 + c4];
#pragma unroll
            for (int cc = 0; cc < 4; cc++) {
                float vv[4];
#pragma unroll
                for (int jj = 0; jj < 4; jj++)
                    vv[jj] = Vs[(c4 + cc) * 68 + jj * 16 + tx];
#pragma unroll
                for (int i = 0; i < 4; i++)
#pragma unroll
                    for (int jj = 0; jj < 4; jj++)
                        acc[i][jj] += pa[i][cc] * vv[jj];
            }
        }
    }

#pragma unroll
    for (int i = 0; i < 4; i++) {
        const float inv = 1.0f / l_run[i];
        const int row = b * Ss + qt * 64 + ty * 4 + i;
#pragma unroll
        for (int jj = 0; jj < 4; jj++)
            g_att[row * Ee + h * 64 + jj * 16 + tx] = acc[i][jj] * inv;
    }
}

// ---------------------------------------------------------------------------
extern "C" void kernel_launch(void* const* d_in, const int* in_sizes, int n_in,
                              void* d_out, int out_size)
{
    (void)in_sizes; (void)n_in; (void)out_size;
    const float* x  = (const float*)d_in[0];
    const float* Wq = (const float*)d_in[1];
    const float* Wk = (const float*)d_in[2];
    const float* Wv = (const float*)d_in[3];
    const float* Wp = (const float*)d_in[4];
    const float* bp = (const float*)d_in[5];
    float* out = (float*)d_out;

    cudaFuncSetAttribute(attn_kernel,
                         cudaFuncAttributeMaxDynamicSharedMemorySize, ATTN_SMEM);
    cudaFuncSetAttribute(gemm_mma_kernel,
                         cudaFuncAttributeMaxDynamicSharedMemorySize, GEMM_SMEM);

    transpose_w_kernel<<<1024, 1024>>>(Wq, Wk, Wv, Wp);
    gemm_mma_kernel<<<dim3(128, 4, 3), 256, GEMM_SMEM>>>(x, -1, nullptr, nullptr);
    attn_kernel<<<dim3(Ss / 64, Hh, Bb), 256, ATTN_SMEM>>>();
    gemm_mma_kernel<<<dim3(128, 4, 1), 256, GEMM_SMEM>>>(x, 3, bp, out);
}

// round 10
// speedup vs baseline: 3.5783x; 2.3094x over previous
#include <cuda_runtime.h>
#include <math.h>
#include <cstdint>

#define Bb 8
#define Ss 2048
#define Ee 512
#define Hh 8
#define Dd 64

// Scratch (device globals — no allocations allowed)
__device__ float g_Q [Bb*Hh*Ss*Dd];   // [b,h,s,d]  tf32, pre-scaled by 0.125*log2e
__device__ float g_K [Bb*Hh*Ss*Dd];   // [b,h,s,d]  tf32
__device__ float g_Vt[Bb*Hh*Dd*Ss];   // [b,h,d,s]  tf32 (V transposed)
__device__ float g_att[Bb*Ss*Ee];     // [b*s, h*d] attention output (fp32)
__device__ float g_Wt[4*Ee*Ee];       // [proj][n][k] transposed weights (tf32)

#define QSC 0.180336880111120426f     // 0.125 * log2(e)

// ---------------------------------------------------------------------------
__device__ __forceinline__ uint32_t smem_u32(const void* p) {
    uint32_t a;
    asm("{ .reg .u64 t; cvta.to.shared.u64 t, %1; cvt.u32.u64 %0, t; }" : "=r"(a) : "l"(p));
    return a;
}
#define CP_ASYNC16(dst_u32, src_ptr) \
    asm volatile("cp.async.cg.shared.global [%0], [%1], 16;" \
        :: "r"(dst_u32), "l"(__cvta_generic_to_global(src_ptr)) : "memory")
#define CP_COMMIT() asm volatile("cp.async.commit_group;" ::: "memory")
#define CP_WAIT_1() asm volatile("cp.async.wait_group 1;" ::: "memory")

#define MMA_TF32(c, a, b) \
    asm volatile("mma.sync.aligned.m16n8k8.row.col.f32.tf32.tf32.f32 " \
        "{%0,%1,%2,%3}, {%4,%5,%6,%7}, {%8,%9}, {%0,%1,%2,%3};" \
        : "+f"((c)[0]), "+f"((c)[1]), "+f"((c)[2]), "+f"((c)[3]) \
        : "r"((a)[0]), "r"((a)[1]), "r"((a)[2]), "r"((a)[3]), \
          "r"((b)[0]), "r"((b)[1]))

__device__ __forceinline__ uint32_t f2tf32(float f) {
    uint32_t u;
    asm("cvt.rna.tf32.f32 %0, %1;" : "=r"(u) : "f"(f));
    return u;
}
__device__ __forceinline__ float fexp2(float x) {
    float y;
    asm("ex2.approx.ftz.f32 %0, %1;" : "=f"(y) : "f"(x));
    return y;
}
__device__ __forceinline__ uint32_t fbits(float f) { return __float_as_uint(f); }

// ---------------------------------------------------------------------------
// Weight transpose + tf32 round: g_Wt[p][n][k]
// ---------------------------------------------------------------------------
__global__ __launch_bounds__(1024) void transpose_w_kernel(
    const float* __restrict__ Wq, const float* __restrict__ Wk,
    const float* __restrict__ Wv, const float* __restrict__ Wp)
{
    const int idx = blockIdx.x * 1024 + threadIdx.x;
    const int p = idx >> 18;
    const int r = idx & 262143;
    const int n = r >> 9;
    const int k = r & 511;
    const float* __restrict__ W = (p == 0) ? Wq : (p == 1) ? Wk : (p == 2) ? Wv : Wp;
    float v;
    if (p < 3) {
        const int h = n >> 6, d = n & 63;
        v = W[(h * Ee + k) * Dd + d];
    } else {
        v = W[k * Ee + n];
    }
    g_Wt[idx] = __uint_as_float(f2tf32(v));
}

// ---------------------------------------------------------------------------
// tf32 mma.sync GEMM (as R6): C[16384x512] = A * Wt^T.
// mode: 0=Q (scaled+tf32), 1=K (tf32), 2=V^T (tf32), 3=proj (+bias -> out).
// ---------------------------------------------------------------------------
#define STAGE_F (128*32 + 128*32)
#define GEMM_SMEM (2 * STAGE_F * 4)

__global__ __launch_bounds__(256) void gemm_mma_kernel(
    const float* __restrict__ Aglob, int mode_in,
    const float* __restrict__ bp, float* __restrict__ out)
{
    extern __shared__ float sm[];
    const int tid = threadIdx.x;
    const int wid = tid >> 5;
    const int lane = tid & 31;
    const int g = lane >> 2;
    const int t = lane & 3;
    const int wm = wid & 3;
    const int wn = wid >> 2;

    const int mode = (mode_in < 0) ? (int)blockIdx.z : mode_in;
    const float* __restrict__ Ag = (mode == 3) ? g_att : Aglob;
    const float* __restrict__ Bg = g_Wt + (size_t)mode * (Ee * Ee);
    const int m0 = blockIdx.x * 128;
    const int n0 = blockIdx.y * 128;

    const uint32_t smb = smem_u32(sm);

    float c[2][8][4];
#pragma unroll
    for (int i = 0; i < 2; i++)
#pragma unroll
        for (int j = 0; j < 8; j++)
#pragma unroll
            for (int q = 0; q < 4; q++) c[i][j][q] = 0.0f;

    auto load_stage = [&](int kt) {
        const uint32_t base = smb + (uint32_t)(kt & 1) * (STAGE_F * 4);
        const int k0 = kt * 32;
#pragma unroll
        for (int p = 0; p < 4; p++) {
            const int id = tid + p * 256;
            const int row = id >> 3, ch = id & 7;
            CP_ASYNC16(base + (uint32_t)(row * 128 + ((ch ^ (row & 7)) * 16)),
                       Ag + (size_t)(m0 + row) * Ee + k0 + ch * 4);
        }
        const uint32_t bbase = base + 128 * 32 * 4;
#pragma unroll
        for (int p = 0; p < 4; p++) {
            const int id = tid + p * 256;
            const int row = id >> 3, ch = id & 7;
            CP_ASYNC16(bbase + (uint32_t)(row * 128 + ((ch ^ (row & 7)) * 16)),
                       Bg + (size_t)(n0 + row) * Ee + k0 + ch * 4);
        }
    };

    load_stage(0);
    CP_COMMIT();

    const int NT = Ee / 32;
    for (int kt = 0; kt < NT; kt++) {
        if (kt + 1 < NT) load_stage(kt + 1);
        CP_COMMIT();
        CP_WAIT_1();
        __syncthreads();

        const float* As = sm + (kt & 1) * STAGE_F;
        const float* Bs = As + 128 * 32;

#pragma unroll
        for (int ks = 0; ks < 4; ks++) {
            const int ch0 = (2 * ks) ^ g;
            const int ch1 = (2 * ks + 1) ^ g;

            uint32_t a[2][4];
#pragma unroll
            for (int i = 0; i < 2; i++) {
                const int row = wm * 32 + i * 16 + g;
                a[i][0] = f2tf32(As[row * 32 + ch0 * 4 + t]);
                a[i][1] = f2tf32(As[(row + 8) * 32 + ch0 * 4 + t]);
                a[i][2] = f2tf32(As[row * 32 + ch1 * 4 + t]);
                a[i][3] = f2tf32(As[(row + 8) * 32 + ch1 * 4 + t]);
            }
            uint32_t b[8][2];
#pragma unroll
            for (int j = 0; j < 8; j++) {
                const int rn = wn * 64 + j * 8 + g;
                b[j][0] = fbits(Bs[rn * 32 + ch0 * 4 + t]);
                b[j][1] = fbits(Bs[rn * 32 + ch1 * 4 + t]);
            }
#pragma unroll
            for (int i = 0; i < 2; i++)
#pragma unroll
                for (int j = 0; j < 8; j++)
                    MMA_TF32(c[i][j], a[i], b[j]);
        }
        __syncthreads();
    }

    // Epilogue. Fragment (i,j): rows m0+wm*32+i*16+g (+8), cols n0+wn*64+j*8+2t (+1)
#pragma unroll
    for (int i = 0; i < 2; i++) {
        const int mrow = m0 + wm * 32 + i * 16 + g;
#pragma unroll
        for (int rr = 0; rr < 2; rr++) {
            const int m = mrow + rr * 8;
            const int b_ = m >> 11;
            const int s = m & 2047;
#pragma unroll
            for (int j = 0; j < 8; j++) {
                const int n = n0 + wn * 64 + j * 8 + 2 * t;
                const float v0 = c[i][j][rr * 2 + 0];
                const float v1 = c[i][j][rr * 2 + 1];
                const int h = n >> 6, d = n & 63;
                if (mode == 0) {
                    float* dst = g_Q + (((size_t)(b_ * Hh + h) * Ss + s) * Dd + d);
                    *(float2*)dst = make_float2(
                        __uint_as_float(f2tf32(v0 * QSC)),
                        __uint_as_float(f2tf32(v1 * QSC)));
                } else if (mode == 1) {
                    float* dst = g_K + (((size_t)(b_ * Hh + h) * Ss + s) * Dd + d);
                    *(float2*)dst = make_float2(
                        __uint_as_float(f2tf32(v0)), __uint_as_float(f2tf32(v1)));
                } else if (mode == 2) {
                    float* dst = g_Vt + ((size_t)(b_ * Hh + h) * Dd + d) * Ss + s;
                    dst[0]  = __uint_as_float(f2tf32(v0));
                    dst[Ss] = __uint_as_float(f2tf32(v1));
                } else {
                    float* dst = out + (size_t)m * Ee + n;
                    *(float2*)dst = make_float2(v0 + bp[n], v1 + bp[n + 1]);
                }
            }
        }
    }
}

// ---------------------------------------------------------------------------
// Tensor-core flash attention. CTA = (qt: 128 rows, h, b). 8 warps; warp w
// owns rows [w*16, w*16+16) x all 64 kv-cols of each 64-wide tile.
// Online softmax in base-2 (Q pre-scaled by 0.125*log2e). K/V double-buffered.
// SMEM rows padded to 68 floats -> conflict-free fragment LDS (bank=4g+t).
// ---------------------------------------------------------------------------
#define AT_SMEM (68 * 512 * 4)   // Qs 128 + K 2*64 + V 2*64 + P 8*16 rows

__global__ __launch_bounds__(256) void attn_mma_kernel()
{
    extern __shared__ float sm[];
    float* Qs = sm;                       // [128][68]
    float* Kb = sm + 128 * 68;            // [2][64][68]
    float* Vb = Kb + 2 * 64 * 68;         // [2][64][68]
    float* Pw = Vb + 2 * 64 * 68;         // [8][16][68]

    const int qt = blockIdx.x;
    const int h  = blockIdx.y;
    const int b  = blockIdx.z;
    const int tid = threadIdx.x;
    const int w = tid >> 5;
    const int lane = tid & 31;
    const int g = lane >> 2;
    const int t = lane & 3;
    const int Q0 = qt * 128;
    const int wbase = w * 16;
    const int r0 = wbase + g;             // local q-row (and r0+8)

    const size_t bh = (size_t)(b * Hh + h);
    const float* __restrict__ Qg  = g_Q  + (bh * Ss + Q0) * Dd;
    const float* __restrict__ Kg  = g_K  + bh * Ss * Dd;
    const float* __restrict__ Vtg = g_Vt + bh * Dd * Ss;

    const uint32_t smb = smem_u32(sm);
    const uint32_t kb0 = smb + 128 * 68 * 4;
    const uint32_t vb0 = kb0 + 2 * 64 * 68 * 4;

    // Q tile: 128 rows x 16 chunks
#pragma unroll
    for (int p = 0; p < 8; p++) {
        const int id = tid + p * 256;
        const int r = id >> 4, cc = id & 15;
        CP_ASYNC16(smb + (uint32_t)(r * 68 + cc * 4) * 4, Qg + r * Dd + cc * 4);
    }
    auto issue_kv = [&](int j) {
        const uint32_t kd = kb0 + (uint32_t)(j & 1) * (64 * 68 * 4);
        const uint32_t vd = vb0 + (uint32_t)(j & 1) * (64 * 68 * 4);
#pragma unroll
        for (int p = 0; p < 4; p++) {
            const int id = tid + p * 256;
            const int r = id >> 4, cc = id & 15;
            CP_ASYNC16(kd + (uint32_t)(r * 68 + cc * 4) * 4,
                       Kg + (size_t)(j * 64 + r) * Dd + cc * 4);
            CP_ASYNC16(vd + (uint32_t)(r * 68 + cc * 4) * 4,
                       Vtg + (size_t)r * Ss + j * 64 + cc * 4);
        }
    };
    issue_kv(0);
    CP_COMMIT();

    float o[8][4];
#pragma unroll
    for (int j = 0; j < 8; j++)
#pragma unroll
        for (int q = 0; q < 4; q++) o[j][q] = 0.0f;
    float mr0 = -1e30f, mr1 = -1e30f, lr0 = 0.0f, lr1 = 0.0f;

    float* Pf = Pw + w * 16 * 68;
    const int jmax = 2 * qt + 1;

    for (int j = 0; j <= jmax; j++) {
        if (j < jmax) issue_kv(j + 1);
        CP_COMMIT();
        CP_WAIT_1();
        __syncthreads();

        // Skip fully-masked tiles for this warp's rows (keep barriers!)
        if (j * 64 <= Q0 + wbase + 15) {
            const float* Ks = Kb + (j & 1) * 64 * 68;
            const float* Vs = Vb + (j & 1) * 64 * 68;

            // ---- S = Q K^T (tf32 mma) ----
            float c[8][4];
#pragma unroll
            for (int jn = 0; jn < 8; jn++)
#pragma unroll
                for (int q = 0; q < 4; q++) c[jn][q] = 0.0f;

#pragma unroll
            for (int ks = 0; ks < 8; ks++) {
                uint32_t a[4];
                a[0] = fbits(Qs[r0 * 68 + ks * 8 + t]);
                a[1] = fbits(Qs[(r0 + 8) * 68 + ks * 8 + t]);
                a[2] = fbits(Qs[r0 * 68 + ks * 8 + t + 4]);
                a[3] = fbits(Qs[(r0 + 8) * 68 + ks * 8 + t + 4]);
#pragma unroll
                for (int jn = 0; jn < 8; jn++) {
                    uint32_t bb[2];
                    bb[0] = fbits(Ks[(jn * 8 + g) * 68 + ks * 8 + t]);
                    bb[1] = fbits(Ks[(jn * 8 + g) * 68 + ks * 8 + t + 4]);
                    MMA_TF32(c[jn], a, bb);
                }
            }

            // ---- causal mask (diagonal tiles only) ----
            if (j >= 2 * qt) {
                const int cb = (j - 2 * qt) * 64;
#pragma unroll
                for (int jn = 0; jn < 8; jn++) {
                    const int c0 = cb + jn * 8 + 2 * t;
                    if (c0     > r0)     c[jn][0] = -1e30f;
                    if (c0 + 1 > r0)     c[jn][1] = -1e30f;
                    if (c0     > r0 + 8) c[jn][2] = -1e30f;
                    if (c0 + 1 > r0 + 8) c[jn][3] = -1e30f;
                }
            }

            // ---- online softmax (base-2), warp-local rows ----
            float tm0 = -1e30f, tm1 = -1e30f;
#pragma unroll
            for (int jn = 0; jn < 8; jn++) {
                tm0 = fmaxf(tm0, fmaxf(c[jn][0], c[jn][1]));
                tm1 = fmaxf(tm1, fmaxf(c[jn][2], c[jn][3]));
            }
            tm0 = fmaxf(tm0, __shfl_xor_sync(0xffffffffu, tm0, 1));
            tm0 = fmaxf(tm0, __shfl_xor_sync(0xffffffffu, tm0, 2));
            tm1 = fmaxf(tm1, __shfl_xor_sync(0xffffffffu, tm1, 1));
            tm1 = fmaxf(tm1, __shfl_xor_sync(0xffffffffu, tm1, 2));

            const float mn0 = fmaxf(mr0, tm0);
            const float mn1 = fmaxf(mr1, tm1);
            const float al0 = fexp2(mr0 - mn0);
            const float al1 = fexp2(mr1 - mn1);
            mr0 = mn0; mr1 = mn1;

            float sum0 = 0.0f, sum1 = 0.0f;
#pragma unroll
            for (int jn = 0; jn < 8; jn++) {
                const float p0 = fexp2(c[jn][0] - mn0);
                const float p1 = fexp2(c[jn][1] - mn0);
                const float p2 = fexp2(c[jn][2] - mn1);
                const float p3 = fexp2(c[jn][3] - mn1);
                sum0 += p0 + p1;
                sum1 += p2 + p3;
                *(uint2*)&Pf[g * 68 + jn * 8 + 2 * t] =
                    make_uint2(f2tf32(p0), f2tf32(p1));
                *(uint2*)&Pf[(g + 8) * 68 + jn * 8 + 2 * t] =
                    make_uint2(f2tf32(p2), f2tf32(p3));
            }
            sum0 += __shfl_xor_sync(0xffffffffu, sum0, 1);
            sum0 += __shfl_xor_sync(0xffffffffu, sum0, 2);
            sum1 += __shfl_xor_sync(0xffffffffu, sum1, 1);
            sum1 += __shfl_xor_sync(0xffffffffu, sum1, 2);
            lr0 = lr0 * al0 + sum0;
            lr1 = lr1 * al1 + sum1;

#pragma unroll
            for (int jn = 0; jn < 8; jn++) {
                o[jn][0] *= al0; o[jn][1] *= al0;
                o[jn][2] *= al1; o[jn][3] *= al1;
            }
            __syncwarp();

            // ---- O += P @ V (tf32 mma; V^T is K-major in SMEM) ----
#pragma unroll
            for (int ks = 0; ks < 8; ks++) {
                uint32_t a[4];
                a[0] = fbits(Pf[g * 68 + ks * 8 + t]);
                a[1] = fbits(Pf[(g + 8) * 68 + ks * 8 + t]);
                a[2] = fbits(Pf[g * 68 + ks * 8 + t + 4]);
                a[3] = fbits(Pf[(g + 8) * 68 + ks * 8 + t + 4]);
#pragma unroll
                for (int jn = 0; jn < 8; jn++) {
                    uint32_t bb[2];
                    bb[0] = fbits(Vs[(jn * 8 + g) * 68 + ks * 8 + t]);
                    bb[1] = fbits(Vs[(jn * 8 + g) * 68 + ks * 8 + t + 4]);
                    MMA_TF32(o[jn], a, bb);
                }
            }
        }
        __syncthreads();
    }

    // ---- epilogue: normalize, write [b*s][h*64+d] ----
    const float i0 = 1.0f / lr0;
    const float i1 = 1.0f / lr1;
    const size_t row0 = ((size_t)b * Ss + Q0 + wbase + g) * Ee + h * 64;
    const size_t row1 = row0 + 8 * Ee;
#pragma unroll
    for (int jn = 0; jn < 8; jn++) {
        const int d = jn * 8 + 2 * t;
        *(float2*)&g_att[row0 + d] = make_float2(o[jn][0] * i0, o[jn][1] * i0);
        *(float2*)&g_att[row1 + d] = make_float2(o[jn][2] * i1, o[jn][3] * i1);
    }
}

// ---------------------------------------------------------------------------
extern "C" void kernel_launch(void* const* d_in, const int* in_sizes, int n_in,
                              void* d_out, int out_size)
{
    (void)in_sizes; (void)n_in; (void)out_size;
    const float* x  = (const float*)d_in[0];
    const float* Wq = (const float*)d_in[1];
    const float* Wk = (const float*)d_in[2];
    const float* Wv = (const float*)d_in[3];
    const float* Wp = (const float*)d_in[4];
    const float* bp = (const float*)d_in[5];
    float* out = (float*)d_out;

    cudaFuncSetAttribute(gemm_mma_kernel,
                         cudaFuncAttributeMaxDynamicSharedMemorySize, GEMM_SMEM);
    cudaFuncSetAttribute(attn_mma_kernel,
                         cudaFuncAttributeMaxDynamicSharedMemorySize, AT_SMEM);

    transpose_w_kernel<<<1024, 1024>>>(Wq, Wk, Wv, Wp);
    gemm_mma_kernel<<<dim3(128, 4, 3), 256, GEMM_SMEM>>>(x, -1, nullptr, nullptr);
    attn_mma_kernel<<<dim3(Ss / 128, Hh, Bb), 256, AT_SMEM>>>();
    gemm_mma_kernel<<<dim3(128, 4, 1), 256, GEMM_SMEM>>>(x, 3, bp, out);
}

// round 12
// speedup vs baseline: 5.3340x; 1.4906x over previous
#include <cuda_runtime.h>
#include <cuda_fp16.h>
#include <math.h>
#include <cstdint>

#define Bb 8
#define Ss 2048
#define Ee 512
#define Hh 8
#define Dd 64

// Scratch (device globals — no allocations allowed)
__device__ __half g_Qh[Bb*Hh*Ss*Dd];  // [b,h,s,d] fp16, pre-scaled by 0.125*log2e
__device__ __half g_Kh[Bb*Hh*Ss*Dd];  // [b,h,s,d] fp16
__device__ __half g_Vh[Bb*Hh*Dd*Ss];  // [b,h,d,s] fp16 (V transposed)
__device__ float  g_att[Bb*Ss*Ee];    // [b*s, h*d] attention output (fp32)
__device__ float  g_Wt[4*Ee*Ee];      // [proj][n][k] transposed weights (tf32)

#define QSC 0.180336880111120426f     // 0.125 * log2(e)

// ---------------------------------------------------------------------------
__device__ __forceinline__ uint32_t smem_u32(const void* p) {
    uint32_t a;
    asm("{ .reg .u64 t; cvta.to.shared.u64 t, %1; cvt.u32.u64 %0, t; }" : "=r"(a) : "l"(p));
    return a;
}
#define CP_ASYNC16(dst_u32, src_ptr) \
    asm volatile("cp.async.cg.shared.global [%0], [%1], 16;" \
        :: "r"(dst_u32), "l"(__cvta_generic_to_global(src_ptr)) : "memory")
#define CP_COMMIT() asm volatile("cp.async.commit_group;" ::: "memory")
#define CP_WAIT_1() asm volatile("cp.async.wait_group 1;" ::: "memory")

#define MMA_TF32(c, a, b) \
    asm volatile("mma.sync.aligned.m16n8k8.row.col.f32.tf32.tf32.f32 " \
        "{%0,%1,%2,%3}, {%4,%5,%6,%7}, {%8,%9}, {%0,%1,%2,%3};" \
        : "+f"((c)[0]), "+f"((c)[1]), "+f"((c)[2]), "+f"((c)[3]) \
        : "r"((a)[0]), "r"((a)[1]), "r"((a)[2]), "r"((a)[3]), \
          "r"((b)[0]), "r"((b)[1]))

#define MMA_F16(c, a, b) \
    asm volatile("mma.sync.aligned.m16n8k16.row.col.f32.f16.f16.f32 " \
        "{%0,%1,%2,%3}, {%4,%5,%6,%7}, {%8,%9}, {%0,%1,%2,%3};" \
        : "+f"((c)[0]), "+f"((c)[1]), "+f"((c)[2]), "+f"((c)[3]) \
        : "r"((a)[0]), "r"((a)[1]), "r"((a)[2]), "r"((a)[3]), \
          "r"((b)[0]), "r"((b)[1]))

__device__ __forceinline__ uint32_t f2tf32(float f) {
    uint32_t u;
    asm("cvt.rna.tf32.f32 %0, %1;" : "=r"(u) : "f"(f));
    return u;
}
__device__ __forceinline__ float fexp2(float x) {
    float y;
    asm("ex2.approx.ftz.f32 %0, %1;" : "=f"(y) : "f"(x));
    return y;
}
__device__ __forceinline__ uint32_t fbits(float f) { return __float_as_uint(f); }
__device__ __forceinline__ uint32_t pack_h2(float lo, float hi) {
    __half2 h = __floats2half2_rn(lo, hi);
    return *(uint32_t*)&h;
}

// ---------------------------------------------------------------------------
// Weight transpose + tf32 round: g_Wt[p][n][k]
// ---------------------------------------------------------------------------
__global__ __launch_bounds__(1024) void transpose_w_kernel(
    const float* __restrict__ Wq, const float* __restrict__ Wk,
    const float* __restrict__ Wv, const float* __restrict__ Wp)
{
    const int idx = blockIdx.x * 1024 + threadIdx.x;
    const int p = idx >> 18;
    const int r = idx & 262143;
    const int n = r >> 9;
    const int k = r & 511;
    const float* __restrict__ W = (p == 0) ? Wq : (p == 1) ? Wk : (p == 2) ? Wv : Wp;
    float v;
    if (p < 3) {
        const int h = n >> 6, d = n & 63;
        v = W[(h * Ee + k) * Dd + d];
    } else {
        v = W[k * Ee + n];
    }
    g_Wt[idx] = __uint_as_float(f2tf32(v));
}

// ---------------------------------------------------------------------------
// tf32 mma.sync GEMM: C[16384x512] = A * Wt^T.
// mode: 0=Q (fp16, scaled), 1=K (fp16), 2=V^T (fp16), 3=proj (+bias -> out).
// ---------------------------------------------------------------------------
#define STAGE_F (128*32 + 128*32)
#define GEMM_SMEM (2 * STAGE_F * 4)

__global__ __launch_bounds__(256) void gemm_mma_kernel(
    const float* __restrict__ Aglob, int mode_in,
    const float* __restrict__ bp, float* __restrict__ out)
{
    extern __shared__ float sm[];
    const int tid = threadIdx.x;
    const int wid = tid >> 5;
    const int lane = tid & 31;
    const int g = lane >> 2;
    const int t = lane & 3;
    const int wm = wid & 3;
    const int wn = wid >> 2;

    const int mode = (mode_in < 0) ? (int)blockIdx.z : mode_in;
    const float* __restrict__ Ag = (mode == 3) ? g_att : Aglob;
    const float* __restrict__ Bg = g_Wt + (size_t)mode * (Ee * Ee);
    const int m0 = blockIdx.x * 128;
    const int n0 = blockIdx.y * 128;

    const uint32_t smb = smem_u32(sm);

    float c[2][8][4];
#pragma unroll
    for (int i = 0; i < 2; i++)
#pragma unroll
        for (int j = 0; j < 8; j++)
#pragma unroll
            for (int q = 0; q < 4; q++) c[i][j][q] = 0.0f;

    auto load_stage = [&](int kt) {
        const uint32_t base = smb + (uint32_t)(kt & 1) * (STAGE_F * 4);
        const int k0 = kt * 32;
#pragma unroll
        for (int p = 0; p < 4; p++) {
            const int id = tid + p * 256;
            const int row = id >> 3, ch = id & 7;
            CP_ASYNC16(base + (uint32_t)(row * 128 + ((ch ^ (row & 7)) * 16)),
                       Ag + (size_t)(m0 + row) * Ee + k0 + ch * 4);
        }
        const uint32_t bbase = base + 128 * 32 * 4;
#pragma unroll
        for (int p = 0; p < 4; p++) {
            const int id = tid + p * 256;
            const int row = id >> 3, ch = id & 7;
            CP_ASYNC16(bbase + (uint32_t)(row * 128 + ((ch ^ (row & 7)) * 16)),
                       Bg + (size_t)(n0 + row) * Ee + k0 + ch * 4);
        }
    };

    load_stage(0);
    CP_COMMIT();

    const int NT = Ee / 32;
    for (int kt = 0; kt < NT; kt++) {
        if (kt + 1 < NT) load_stage(kt + 1);
        CP_COMMIT();
        CP_WAIT_1();
        __syncthreads();

        const float* As = sm + (kt & 1) * STAGE_F;
        const float* Bs = As + 128 * 32;

#pragma unroll
        for (int ks = 0; ks < 4; ks++) {
            const int ch0 = (2 * ks) ^ g;
            const int ch1 = (2 * ks + 1) ^ g;

            uint32_t a[2][4];
#pragma unroll
            for (int i = 0; i < 2; i++) {
                const int row = wm * 32 + i * 16 + g;
                a[i][0] = f2tf32(As[row * 32 + ch0 * 4 + t]);
                a[i][1] = f2tf32(As[(row + 8) * 32 + ch0 * 4 + t]);
                a[i][2] = f2tf32(As[row * 32 + ch1 * 4 + t]);
                a[i][3] = f2tf32(As[(row + 8) * 32 + ch1 * 4 + t]);
            }
            uint32_t b[8][2];
#pragma unroll
            for (int j = 0; j < 8; j++) {
                const int rn = wn * 64 + j * 8 + g;
                b[j][0] = fbits(Bs[rn * 32 + ch0 * 4 + t]);
                b[j][1] = fbits(Bs[rn * 32 + ch1 * 4 + t]);
            }
#pragma unroll
            for (int i = 0; i < 2; i++)
#pragma unroll
                for (int j = 0; j < 8; j++)
                    MMA_TF32(c[i][j], a[i], b[j]);
        }
        __syncthreads();
    }

    // Epilogue. Fragment (i,j): rows m0+wm*32+i*16+g (+8), cols n0+wn*64+j*8+2t (+1)
#pragma unroll
    for (int i = 0; i < 2; i++) {
        const int mrow = m0 + wm * 32 + i * 16 + g;
#pragma unroll
        for (int rr = 0; rr < 2; rr++) {
            const int m = mrow + rr * 8;
            const int b_ = m >> 11;
            const int s = m & 2047;
#pragma unroll
            for (int j = 0; j < 8; j++) {
                const int n = n0 + wn * 64 + j * 8 + 2 * t;
                const float v0 = c[i][j][rr * 2 + 0];
                const float v1 = c[i][j][rr * 2 + 1];
                const int h = n >> 6, d = n & 63;
                const size_t bh = (size_t)(b_ * Hh + h);
                if (mode == 0) {
                    __half2* dst = (__half2*)(g_Qh + (bh * Ss + s) * Dd + d);
                    *dst = __floats2half2_rn(v0 * QSC, v1 * QSC);
                } else if (mode == 1) {
                    __half2* dst = (__half2*)(g_Kh + (bh * Ss + s) * Dd + d);
                    *dst = __floats2half2_rn(v0, v1);
                } else if (mode == 2) {
                    __half* dst = g_Vh + (bh * Dd + d) * Ss + s;
                    dst[0]  = __float2half_rn(v0);
                    dst[Ss] = __float2half_rn(v1);
                } else {
                    float* dst = out + (size_t)m * Ee + n;
                    *(float2*)dst = make_float2(v0 + bp[n], v1 + bp[n + 1]);
                }
            }
        }
    }
}

// ---------------------------------------------------------------------------
// fp16 flash attention, P kept in registers. CTA = (qt: 128 q-rows, h, b).
// 8 warps; warp w owns rows [w*16, w*16+16) x all 64 kv-cols per 64-wide tile.
// m16n8k16 f16 MMAs, fp32 accum. SMEM row stride 72 halves (144B: bank-clean).
// SMEM = Q 128x72 + K 2x64x72 + V 2x64x72 halves = 54 KB -> 2 CTAs/SM.
// ---------------------------------------------------------------------------
#define AT_SMEM ((128*72 + 4*64*72) * 2)

__global__ __launch_bounds__(256, 2) void attn_f16_kernel()
{
    extern __shared__ float sm[];
    __half* Qs = (__half*)sm;             // [128][72]
    __half* Kb = Qs + 128 * 72;           // [2][64][72]
    __half* Vb = Kb + 2 * 64 * 72;        // [2][64][72]

    const int qt = blockIdx.x;
    const int h  = blockIdx.y;
    const int b  = blockIdx.z;
    const int tid = threadIdx.x;
    const int w = tid >> 5;
    const int lane = tid & 31;
    const int g = lane >> 2;
    const int t = lane & 3;
    const int Q0 = qt * 128;
    const int wbase = w * 16;
    const int r0 = wbase + g;

    const size_t bh = (size_t)(b * Hh + h);
    const __half* __restrict__ Qg = g_Qh + (bh * Ss + Q0) * Dd;
    const __half* __restrict__ Kg = g_Kh + bh * Ss * Dd;
    const __half* __restrict__ Vg = g_Vh + bh * Dd * Ss;

    const uint32_t smb = smem_u32(sm);
    const uint32_t kb0 = smb + 128 * 72 * 2;
    const uint32_t vb0 = kb0 + 2 * 64 * 72 * 2;

    // Q tile: 128 rows x 8 chunks (16B = 8 halves)
#pragma unroll
    for (int p = 0; p < 4; p++) {
        const int id = tid + p * 256;
        const int r = id >> 3, ch = id & 7;
        CP_ASYNC16(smb + (uint32_t)(r * 72 + ch * 8) * 2, Qg + r * Dd + ch * 8);
    }
    auto issue_kv = [&](int j) {
        const uint32_t kd = kb0 + (uint32_t)(j & 1) * (64 * 72 * 2);
        const uint32_t vd = vb0 + (uint32_t)(j & 1) * (64 * 72 * 2);
#pragma unroll
        for (int p = 0; p < 2; p++) {
            const int id = tid + p * 256;
            const int r = id >> 3, ch = id & 7;
            CP_ASYNC16(kd + (uint32_t)(r * 72 + ch * 8) * 2,
                       Kg + (size_t)(j * 64 + r) * Dd + ch * 8);
            CP_ASYNC16(vd + (uint32_t)(r * 72 + ch * 8) * 2,
                       Vg + (size_t)r * Ss + j * 64 + ch * 8);
        }
    };
    issue_kv(0);
    CP_COMMIT();

    float o[8][4];
#pragma unroll
    for (int j = 0; j < 8; j++)
#pragma unroll
        for (int q = 0; q < 4; q++) o[j][q] = 0.0f;
    float mr0 = -1e30f, mr1 = -1e30f, lr0 = 0.0f, lr1 = 0.0f;

    const int jmax = 2 * qt + 1;

    for (int j = 0; j <= jmax; j++) {
        if (j < jmax) issue_kv(j + 1);
        CP_COMMIT();
        CP_WAIT_1();
        __syncthreads();

        if (j * 64 <= Q0 + wbase + 15) {     // warp has unmasked work
            const __half* Ks = Kb + (j & 1) * 64 * 72;
            const __half* Vs = Vb + (j & 1) * 64 * 72;

            // ---- S = Q K^T (f16 mma, fp32 accum) ----
            float c[8][4];
#pragma unroll
            for (int jn = 0; jn < 8; jn++)
#pragma unroll
                for (int q = 0; q < 4; q++) c[jn][q] = 0.0f;

#pragma unroll
            for (int ks = 0; ks < 4; ks++) {
                uint32_t a[4];
                a[0] = *(const uint32_t*)&Qs[r0 * 72 + ks * 16 + 2 * t];
                a[1] = *(const uint32_t*)&Qs[(r0 + 8) * 72 + ks * 16 + 2 * t];
                a[2] = *(const uint32_t*)&Qs[r0 * 72 + ks * 16 + 2 * t + 8];
                a[3] = *(const uint32_t*)&Qs[(r0 + 8) * 72 + ks * 16 + 2 * t + 8];
#pragma unroll
                for (int jn = 0; jn < 8; jn++) {
                    uint32_t bb[2];
                    bb[0] = *(const uint32_t*)&Ks[(jn * 8 + g) * 72 + ks * 16 + 2 * t];
                    bb[1] = *(const uint32_t*)&Ks[(jn * 8 + g) * 72 + ks * 16 + 2 * t + 8];
                    MMA_F16(c[jn], a, bb);
                }
            }

            // ---- causal mask (diagonal tiles only) ----
            if (j >= 2 * qt) {
                const int cb = (j - 2 * qt) * 64;
#pragma unroll
                for (int jn = 0; jn < 8; jn++) {
                    const int c0 = cb + jn * 8 + 2 * t;
                    if (c0     > r0)     c[jn][0] = -1e30f;
                    if (c0 + 1 > r0)     c[jn][1] = -1e30f;
                    if (c0     > r0 + 8) c[jn][2] = -1e30f;
                    if (c0 + 1 > r0 + 8) c[jn][3] = -1e30f;
                }
            }

            // ---- online softmax (base-2), warp-local rows ----
            float tm0 = -1e30f, tm1 = -1e30f;
#pragma unroll
            for (int jn = 0; jn < 8; jn++) {
                tm0 = fmaxf(tm0, fmaxf(c[jn][0], c[jn][1]));
                tm1 = fmaxf(tm1, fmaxf(c[jn][2], c[jn][3]));
            }
            tm0 = fmaxf(tm0, __shfl_xor_sync(0xffffffffu, tm0, 1));
            tm0 = fmaxf(tm0, __shfl_xor_sync(0xffffffffu, tm0, 2));
            tm1 = fmaxf(tm1, __shfl_xor_sync(0xffffffffu, tm1, 1));
            tm1 = fmaxf(tm1, __shfl_xor_sync(0xffffffffu, tm1, 2));

            const float mn0 = fmaxf(mr0, tm0);
            const float mn1 = fmaxf(mr1, tm1);
            const float al0 = fexp2(mr0 - mn0);
            const float al1 = fexp2(mr1 - mn1);
            mr0 = mn0; mr1 = mn1;

            float sum0 = 0.0f, sum1 = 0.0f;
#pragma unroll
            for (int jn = 0; jn < 8; jn++) {
                c[jn][0] = fexp2(c[jn][0] - mn0);
                c[jn][1] = fexp2(c[jn][1] - mn0);
                c[jn][2] = fexp2(c[jn][2] - mn1);
                c[jn][3] = fexp2(c[jn][3] - mn1);
                sum0 += c[jn][0] + c[jn][1];
                sum1 += c[jn][2] + c[jn][3];
            }
            sum0 += __shfl_xor_sync(0xffffffffu, sum0, 1);
            sum0 += __shfl_xor_sync(0xffffffffu, sum0, 2);
            sum1 += __shfl_xor_sync(0xffffffffu, sum1, 1);
            sum1 += __shfl_xor_sync(0xffffffffu, sum1, 2);
            lr0 = lr0 * al0 + sum0;
            lr1 = lr1 * al1 + sum1;

#pragma unroll
            for (int jn = 0; jn < 8; jn++) {
                o[jn][0] *= al0; o[jn][1] *= al0;
                o[jn][2] *= al1; o[jn][3] *= al1;
            }

            // ---- O += P @ V (P packed from registers; V^T K-major in SMEM) ----
#pragma unroll
            for (int ks = 0; ks < 4; ks++) {
                uint32_t a[4];
                a[0] = pack_h2(c[2 * ks][0],     c[2 * ks][1]);
                a[1] = pack_h2(c[2 * ks][2],     c[2 * ks][3]);
                a[2] = pack_h2(c[2 * ks + 1][0], c[2 * ks + 1][1]);
                a[3] = pack_h2(c[2 * ks + 1][2], c[2 * ks + 1][3]);
#pragma unroll
                for (int jn = 0; jn < 8; jn++) {
                    uint32_t bb[2];
                    bb[0] = *(const uint32_t*)&Vs[(jn * 8 + g) * 72 + ks * 16 + 2 * t];
                    bb[1] = *(const uint32_t*)&Vs[(jn * 8 + g) * 72 + ks * 16 + 2 * t + 8];
                    MMA_F16(o[jn], a, bb);
                }
            }
        }
        __syncthreads();
    }

    // ---- epilogue: normalize, write [b*s][h*64+d] ----
    const float i0 = 1.0f / lr0;
    const float i1 = 1.0f / lr1;
    const size_t row0 = ((size_t)b * Ss + Q0 + wbase + g) * Ee + h * 64;
    const size_t row1 = row0 + 8 * Ee;
#pragma unroll
    for (int jn = 0; jn < 8; jn++) {
        const int d = jn * 8 + 2 * t;
        *(float2*)&g_att[row0 + d] = make_float2(o[jn][0] * i0, o[jn][1] * i0);
        *(float2*)&g_att[row1 + d] = make_float2(o[jn][2] * i1, o[jn][3] * i1);
    }
}

// ---------------------------------------------------------------------------
extern "C" void kernel_launch(void* const* d_in, const int* in_sizes, int n_in,
                              void* d_out, int out_size)
{
    (void)in_sizes; (void)n_in; (void)out_size;
    const float* x  = (const float*)d_in[0];
    const float* Wq = (const float*)d_in[1];
    const float* Wk = (const float*)d_in[2];
    const float* Wv = (const float*)d_in[3];
    const float* Wp = (const float*)d_in[4];
    const float* bp = (const float*)d_in[5];
    float* out = (float*)d_out;

    cudaFuncSetAttribute(gemm_mma_kernel,
                         cudaFuncAttributeMaxDynamicSharedMemorySize, GEMM_SMEM);
    cudaFuncSetAttribute(attn_f16_kernel,
                         cudaFuncAttributeMaxDynamicSharedMemorySize, AT_SMEM);

    transpose_w_kernel<<<1024, 1024>>>(Wq, Wk, Wv, Wp);
    gemm_mma_kernel<<<dim3(128, 4, 3), 256, GEMM_SMEM>>>(x, -1, nullptr, nullptr);
    attn_f16_kernel<<<dim3(Ss / 128, Hh, Bb), 256, AT_SMEM>>>();
    gemm_mma_kernel<<<dim3(128, 4, 1), 256, GEMM_SMEM>>>(x, 3, bp, out);
}

// round 14
// speedup vs baseline: 5.5236x; 1.0355x over previous
#include <cuda_runtime.h>
#include <cuda_fp16.h>
#include <math.h>
#include <cstdint>

#define Bb 8
#define Ss 2048
#define Ee 512
#define Hh 8
#define Dd 64

// Scratch (device globals — no allocations allowed)
__device__ __half g_Qh[Bb*Hh*Ss*Dd];  // [b,h,s,d] fp16, pre-scaled by 0.125*log2e
__device__ __half g_Kh[Bb*Hh*Ss*Dd];  // [b,h,s,d] fp16
__device__ __half g_Vh[Bb*Hh*Dd*Ss];  // [b,h,d,s] fp16 (V transposed)
__device__ float  g_att[Bb*Ss*Ee];    // [b*s, h*d] attention output (fp32)
__device__ float  g_Wt[4*Ee*Ee];      // [proj][n][k] transposed weights (tf32)

#define QSC 0.180336880111120426f     // 0.125 * log2(e)

// ---------------------------------------------------------------------------
__device__ __forceinline__ uint32_t smem_u32(const void* p) {
    uint32_t a;
    asm("{ .reg .u64 t; cvta.to.shared.u64 t, %1; cvt.u32.u64 %0, t; }" : "=r"(a) : "l"(p));
    return a;
}
#define CP_ASYNC16(dst_u32, src_ptr) \
    asm volatile("cp.async.cg.shared.global [%0], [%1], 16;" \
        :: "r"(dst_u32), "l"(__cvta_generic_to_global(src_ptr)) : "memory")
#define CP_COMMIT() asm volatile("cp.async.commit_group;" ::: "memory")
#define CP_WAIT_1() asm volatile("cp.async.wait_group 1;" ::: "memory")

#define MMA_TF32(c, a, b) \
    asm volatile("mma.sync.aligned.m16n8k8.row.col.f32.tf32.tf32.f32 " \
        "{%0,%1,%2,%3}, {%4,%5,%6,%7}, {%8,%9}, {%0,%1,%2,%3};" \
        : "+f"((c)[0]), "+f"((c)[1]), "+f"((c)[2]), "+f"((c)[3]) \
        : "r"((a)[0]), "r"((a)[1]), "r"((a)[2]), "r"((a)[3]), \
          "r"((b)[0]), "r"((b)[1]))

#define MMA_F16(c, a, b) \
    asm volatile("mma.sync.aligned.m16n8k16.row.col.f32.f16.f16.f32 " \
        "{%0,%1,%2,%3}, {%4,%5,%6,%7}, {%8,%9}, {%0,%1,%2,%3};" \
        : "+f"((c)[0]), "+f"((c)[1]), "+f"((c)[2]), "+f"((c)[3]) \
        : "r"((a)[0]), "r"((a)[1]), "r"((a)[2]), "r"((a)[3]), \
          "r"((b)[0]), "r"((b)[1]))

__device__ __forceinline__ uint32_t f2tf32(float f) {
    uint32_t u;
    asm("cvt.rna.tf32.f32 %0, %1;" : "=r"(u) : "f"(f));
    return u;
}
__device__ __forceinline__ float fexp2(float x) {
    float y;
    asm("ex2.approx.ftz.f32 %0, %1;" : "=f"(y) : "f"(x));
    return y;
}
__device__ __forceinline__ uint32_t fbits(float f) { return __float_as_uint(f); }
__device__ __forceinline__ uint32_t pack_h2(float lo, float hi) {
    __half2 h = __floats2half2_rn(lo, hi);
    return *(uint32_t*)&h;
}

// ---------------------------------------------------------------------------
// Weight transpose + tf32 round: g_Wt[p][n][k]
// ---------------------------------------------------------------------------
__global__ __launch_bounds__(1024) void transpose_w_kernel(
    const float* __restrict__ Wq, const float* __restrict__ Wk,
    const float* __restrict__ Wv, const float* __restrict__ Wp)
{
    const int idx = blockIdx.x * 1024 + threadIdx.x;
    const int p = idx >> 18;
    const int r = idx & 262143;
    const int n = r >> 9;
    const int k = r & 511;
    const float* __restrict__ W = (p == 0) ? Wq : (p == 1) ? Wk : (p == 2) ? Wv : Wp;
    float v;
    if (p < 3) {
        const int h = n >> 6, d = n & 63;
        v = W[(h * Ee + k) * Dd + d];
    } else {
        v = W[k * Ee + n];
    }
    g_Wt[idx] = __uint_as_float(f2tf32(v));
}

// ---------------------------------------------------------------------------
// tf32 mma.sync GEMM: C[16384x512] = A * Wt^T.
// mode: 0=Q (fp16, scaled), 1=K (fp16), 2=V^T (fp16), 3=proj (+bias -> out).
// ---------------------------------------------------------------------------
#define STAGE_F (128*32 + 128*32)
#define GEMM_SMEM (2 * STAGE_F * 4)

__global__ __launch_bounds__(256) void gemm_mma_kernel(
    const float* __restrict__ Aglob, int mode_in,
    const float* __restrict__ bp, float* __restrict__ out)
{
    extern __shared__ float sm[];
    const int tid = threadIdx.x;
    const int wid = tid >> 5;
    const int lane = tid & 31;
    const int g = lane >> 2;
    const int t = lane & 3;
    const int wm = wid & 3;
    const int wn = wid >> 2;

    const int mode = (mode_in < 0) ? (int)blockIdx.z : mode_in;
    const float* __restrict__ Ag = (mode == 3) ? g_att : Aglob;
    const float* __restrict__ Bg = g_Wt + (size_t)mode * (Ee * Ee);
    const int m0 = blockIdx.x * 128;
    const int n0 = blockIdx.y * 128;

    const uint32_t smb = smem_u32(sm);

    float c[2][8][4];
#pragma unroll
    for (int i = 0; i < 2; i++)
#pragma unroll
        for (int j = 0; j < 8; j++)
#pragma unroll
            for (int q = 0; q < 4; q++) c[i][j][q] = 0.0f;

    auto load_stage = [&](int kt) {
        const uint32_t base = smb + (uint32_t)(kt & 1) * (STAGE_F * 4);
        const int k0 = kt * 32;
#pragma unroll
        for (int p = 0; p < 4; p++) {
            const int id = tid + p * 256;
            const int row = id >> 3, ch = id & 7;
            CP_ASYNC16(base + (uint32_t)(row * 128 + ((ch ^ (row & 7)) * 16)),
                       Ag + (size_t)(m0 + row) * Ee + k0 + ch * 4);
        }
        const uint32_t bbase = base + 128 * 32 * 4;
#pragma unroll
        for (int p = 0; p < 4; p++) {
            const int id = tid + p * 256;
            const int row = id >> 3, ch = id & 7;
            CP_ASYNC16(bbase + (uint32_t)(row * 128 + ((ch ^ (row & 7)) * 16)),
                       Bg + (size_t)(n0 + row) * Ee + k0 + ch * 4);
        }
    };

    load_stage(0);
    CP_COMMIT();

    const int NT = Ee / 32;
    for (int kt = 0; kt < NT; kt++) {
        if (kt + 1 < NT) load_stage(kt + 1);
        CP_COMMIT();
        CP_WAIT_1();
        __syncthreads();

        const float* As = sm + (kt & 1) * STAGE_F;
        const float* Bs = As + 128 * 32;

#pragma unroll
        for (int ks = 0; ks < 4; ks++) {
            const int ch0 = (2 * ks) ^ g;
            const int ch1 = (2 * ks + 1) ^ g;

            uint32_t a[2][4];
#pragma unroll
            for (int i = 0; i < 2; i++) {
                const int row = wm * 32 + i * 16 + g;
                a[i][0] = f2tf32(As[row * 32 + ch0 * 4 + t]);
                a[i][1] = f2tf32(As[(row + 8) * 32 + ch0 * 4 + t]);
                a[i][2] = f2tf32(As[row * 32 + ch1 * 4 + t]);
                a[i][3] = f2tf32(As[(row + 8) * 32 + ch1 * 4 + t]);
            }
            uint32_t b[8][2];
#pragma unroll
            for (int j = 0; j < 8; j++) {
                const int rn = wn * 64 + j * 8 + g;
                b[j][0] = fbits(Bs[rn * 32 + ch0 * 4 + t]);
                b[j][1] = fbits(Bs[rn * 32 + ch1 * 4 + t]);
            }
#pragma unroll
            for (int i = 0; i < 2; i++)
#pragma unroll
                for (int j = 0; j < 8; j++)
                    MMA_TF32(c[i][j], a[i], b[j]);
        }
        __syncthreads();
    }

    // Epilogue. Fragment (i,j): rows m0+wm*32+i*16+g (+8), cols n0+wn*64+j*8+2t (+1)
#pragma unroll
    for (int i = 0; i < 2; i++) {
        const int mrow = m0 + wm * 32 + i * 16 + g;
#pragma unroll
        for (int rr = 0; rr < 2; rr++) {
            const int m = mrow + rr * 8;
            const int b_ = m >> 11;
            const int s = m & 2047;
#pragma unroll
            for (int j = 0; j < 8; j++) {
                const int n = n0 + wn * 64 + j * 8 + 2 * t;
                const float v0 = c[i][j][rr * 2 + 0];
                const float v1 = c[i][j][rr * 2 + 1];
                const int h = n >> 6, d = n & 63;
                const size_t bh = (size_t)(b_ * Hh + h);
                if (mode == 0) {
                    __half2* dst = (__half2*)(g_Qh + (bh * Ss + s) * Dd + d);
                    *dst = __floats2half2_rn(v0 * QSC, v1 * QSC);
                } else if (mode == 1) {
                    __half2* dst = (__half2*)(g_Kh + (bh * Ss + s) * Dd + d);
                    *dst = __floats2half2_rn(v0, v1);
                } else if (mode == 2) {
                    __half* dst = g_Vh + (bh * Dd + d) * Ss + s;
                    dst[0]  = __float2half_rn(v0);
                    dst[Ss] = __float2half_rn(v1);
                } else {
                    float* dst = out + (size_t)m * Ee + n;
                    *(float2*)dst = make_float2(v0 + bp[n], v1 + bp[n + 1]);
                }
            }
        }
    }
}

// ---------------------------------------------------------------------------
// fp16 flash attention, K/V fragments amortized over 32 q-rows per warp.
// CTA = 4 warps (128 thr), 128 q-rows; warp w owns rows [w*32, w*32+32)
// (two 16-row A-tiles) x all 64 kv-cols per tile. m16n8k16 f16 MMAs, fp32
// accum, P kept in registers. SMEM stride 72 halves; Q 128x72 + K/V 2x64x72
// halves = 54 KB -> 2 CTAs/SM.
// ---------------------------------------------------------------------------
#define AT_SMEM ((128*72 + 4*64*72) * 2)

__global__ __launch_bounds__(128, 2) void attn_f16_kernel()
{
    extern __shared__ float sm[];
    __half* Qs = (__half*)sm;             // [128][72]
    __half* Kb = Qs + 128 * 72;           // [2][64][72]
    __half* Vb = Kb + 2 * 64 * 72;        // [2][64][72]

    const int qt = blockIdx.x;
    const int h  = blockIdx.y;
    const int b  = blockIdx.z;
    const int tid = threadIdx.x;
    const int w = tid >> 5;
    const int lane = tid & 31;
    const int g = lane >> 2;
    const int t = lane & 3;
    const int Q0 = qt * 128;
    const int wbase = w * 32;
    const int r0 = wbase + g;             // rows r0, r0+8, r0+16, r0+24

    const size_t bh = (size_t)(b * Hh + h);
    const __half* __restrict__ Qg = g_Qh + (bh * Ss + Q0) * Dd;
    const __half* __restrict__ Kg = g_Kh + bh * Ss * Dd;
    const __half* __restrict__ Vg = g_Vh + bh * Dd * Ss;

    const uint32_t smb = smem_u32(sm);
    const uint32_t kb0 = smb + 128 * 72 * 2;
    const uint32_t vb0 = kb0 + 2 * 64 * 72 * 2;

    // Q tile: 128 rows x 8 chunks (16B = 8 halves), 128 threads -> 8 iters
#pragma unroll
    for (int p = 0; p < 8; p++) {
        const int id = tid + p * 128;
        const int r = id >> 3, ch = id & 7;
        CP_ASYNC16(smb + (uint32_t)(r * 72 + ch * 8) * 2, Qg + r * Dd + ch * 8);
    }
    auto issue_kv = [&](int j) {
        const uint32_t kd = kb0 + (uint32_t)(j & 1) * (64 * 72 * 2);
        const uint32_t vd = vb0 + (uint32_t)(j & 1) * (64 * 72 * 2);
#pragma unroll
        for (int p = 0; p < 4; p++) {
            const int id = tid + p * 128;
            const int r = id >> 3, ch = id & 7;
            CP_ASYNC16(kd + (uint32_t)(r * 72 + ch * 8) * 2,
                       Kg + (size_t)(j * 64 + r) * Dd + ch * 8);
            CP_ASYNC16(vd + (uint32_t)(r * 72 + ch * 8) * 2,
                       Vg + (size_t)r * Ss + j * 64 + ch * 8);
        }
    };
    issue_kv(0);
    CP_COMMIT();

    float o[2][8][4];
#pragma unroll
    for (int it = 0; it < 2; it++)
#pragma unroll
        for (int j = 0; j < 8; j++)
#pragma unroll
            for (int q = 0; q < 4; q++) o[it][j][q] = 0.0f;
    float mr[2][2] = {{-1e30f, -1e30f}, {-1e30f, -1e30f}};
    float lr[2][2] = {{0.0f, 0.0f}, {0.0f, 0.0f}};

    const int jmax = 2 * qt + 1;

    for (int j = 0; j <= jmax; j++) {
        if (j < jmax) issue_kv(j + 1);
        CP_COMMIT();
        CP_WAIT_1();
        __syncthreads();

        if (j * 64 <= Q0 + wbase + 31) {     // warp has unmasked work
            const __half* Ks = Kb + (j & 1) * 64 * 72;
            const __half* Vs = Vb + (j & 1) * 64 * 72;

            // ---- S = Q K^T: K fragments shared across both A-tiles ----
            float c[2][8][4];
#pragma unroll
            for (int it = 0; it < 2; it++)
#pragma unroll
                for (int jn = 0; jn < 8; jn++)
#pragma unroll
                    for (int q = 0; q < 4; q++) c[it][jn][q] = 0.0f;

#pragma unroll
            for (int ks = 0; ks < 4; ks++) {
                uint32_t bb[8][2];
#pragma unroll
                for (int jn = 0; jn < 8; jn++) {
                    bb[jn][0] = *(const uint32_t*)&Ks[(jn * 8 + g) * 72 + ks * 16 + 2 * t];
                    bb[jn][1] = *(const uint32_t*)&Ks[(jn * 8 + g) * 72 + ks * 16 + 2 * t + 8];
                }
#pragma unroll
                for (int it = 0; it < 2; it++) {
                    const int rr = r0 + it * 16;
                    uint32_t a[4];
                    a[0] = *(const uint32_t*)&Qs[rr * 72 + ks * 16 + 2 * t];
                    a[1] = *(const uint32_t*)&Qs[(rr + 8) * 72 + ks * 16 + 2 * t];
                    a[2] = *(const uint32_t*)&Qs[rr * 72 + ks * 16 + 2 * t + 8];
                    a[3] = *(const uint32_t*)&Qs[(rr + 8) * 72 + ks * 16 + 2 * t + 8];
#pragma unroll
                    for (int jn = 0; jn < 8; jn++)
                        MMA_F16(c[it][jn], a, bb[jn]);
                }
            }

            // ---- causal mask (diagonal tiles only) ----
            if (j * 64 + 63 > Q0 + wbase) {
                const int cb = j * 64 - Q0;    // tile col base in local rows
#pragma unroll
                for (int it = 0; it < 2; it++) {
                    const int ra = r0 + it * 16;
#pragma unroll
                    for (int jn = 0; jn < 8; jn++) {
                        const int c0 = cb + jn * 8 + 2 * t;
                        if (c0     > ra)     c[it][jn][0] = -1e30f;
                        if (c0 + 1 > ra)     c[it][jn][1] = -1e30f;
                        if (c0     > ra + 8) c[it][jn][2] = -1e30f;
                        if (c0 + 1 > ra + 8) c[it][jn][3] = -1e30f;
                    }
                }
            }

            // ---- online softmax (base-2) per A-tile ----
#pragma unroll
            for (int it = 0; it < 2; it++) {
                float tm0 = -1e30f, tm1 = -1e30f;
#pragma unroll
                for (int jn = 0; jn < 8; jn++) {
                    tm0 = fmaxf(tm0, fmaxf(c[it][jn][0], c[it][jn][1]));
                    tm1 = fmaxf(tm1, fmaxf(c[it][jn][2], c[it][jn][3]));
                }
                tm0 = fmaxf(tm0, __shfl_xor_sync(0xffffffffu, tm0, 1));
                tm0 = fmaxf(tm0, __shfl_xor_sync(0xffffffffu, tm0, 2));
                tm1 = fmaxf(tm1, __shfl_xor_sync(0xffffffffu, tm1, 1));
                tm1 = fmaxf(tm1, __shfl_xor_sync(0xffffffffu, tm1, 2));

                const float mn0 = fmaxf(mr[it][0], tm0);
                const float mn1 = fmaxf(mr[it][1], tm1);
                const float al0 = fexp2(mr[it][0] - mn0);
                const float al1 = fexp2(mr[it][1] - mn1);
                mr[it][0] = mn0; mr[it][1] = mn1;

                float sum0 = 0.0f, sum1 = 0.0f;
#pragma unroll
                for (int jn = 0; jn < 8; jn++) {
                    c[it][jn][0] = fexp2(c[it][jn][0] - mn0);
                    c[it][jn][1] = fexp2(c[it][jn][1] - mn0);
                    c[it][jn][2] = fexp2(c[it][jn][2] - mn1);
                    c[it][jn][3] = fexp2(c[it][jn][3] - mn1);
                    sum0 += c[it][jn][0] + c[it][jn][1];
                    sum1 += c[it][jn][2] + c[it][jn][3];
                }
                sum0 += __shfl_xor_sync(0xffffffffu, sum0, 1);
                sum0 += __shfl_xor_sync(0xffffffffu, sum0, 2);
                sum1 += __shfl_xor_sync(0xffffffffu, sum1, 1);
                sum1 += __shfl_xor_sync(0xffffffffu, sum1, 2);
                lr[it][0] = lr[it][0] * al0 + sum0;
                lr[it][1] = lr[it][1] * al1 + sum1;

#pragma unroll
                for (int jn = 0; jn < 8; jn++) {
                    o[it][jn][0] *= al0; o[it][jn][1] *= al0;
                    o[it][jn][2] *= al1; o[it][jn][3] *= al1;
                }
            }

            // ---- O += P @ V: V fragments shared across both A-tiles ----
#pragma unroll
            for (int ks = 0; ks < 4; ks++) {
                uint32_t bb[8][2];
#pragma unroll
                for (int jn = 0; jn < 8; jn++) {
                    bb[jn][0] = *(const uint32_t*)&Vs[(jn * 8 + g) * 72 + ks * 16 + 2 * t];
                    bb[jn][1] = *(const uint32_t*)&Vs[(jn * 8 + g) * 72 + ks * 16 + 2 * t + 8];
                }
#pragma unroll
                for (int it = 0; it < 2; it++) {
                    uint32_t a[4];
                    a[0] = pack_h2(c[it][2 * ks][0],     c[it][2 * ks][1]);
                    a[1] = pack_h2(c[it][2 * ks][2],     c[it][2 * ks][3]);
                    a[2] = pack_h2(c[it][2 * ks + 1][0], c[it][2 * ks + 1][1]);
                    a[3] = pack_h2(c[it][2 * ks + 1][2], c[it][2 * ks + 1][3]);
#pragma unroll
                    for (int jn = 0; jn < 8; jn++)
                        MMA_F16(o[it][jn], a, bb[jn]);
                }
            }
        }
        __syncthreads();
    }

    // ---- epilogue: normalize, write [b*s][h*64+d] ----
#pragma unroll
    for (int it = 0; it < 2; it++) {
        const float i0 = 1.0f / lr[it][0];
        const float i1 = 1.0f / lr[it][1];
        const size_t row0 = ((size_t)b * Ss + Q0 + wbase + it * 16 + g) * Ee + h * 64;
        const size_t row1 = row0 + 8 * Ee;
#pragma unroll
        for (int jn = 0; jn < 8; jn++) {
            const int d = jn * 8 + 2 * t;
            *(float2*)&g_att[row0 + d] =
                make_float2(o[it][jn][0] * i0, o[it][jn][1] * i0);
            *(float2*)&g_att[row1 + d] =
                make_float2(o[it][jn][2] * i1, o[it][jn][3] * i1);
        }
    }
}

// ---------------------------------------------------------------------------
extern "C" void kernel_launch(void* const* d_in, const int* in_sizes, int n_in,
                              void* d_out, int out_size)
{
    (void)in_sizes; (void)n_in; (void)out_size;
    const float* x  = (const float*)d_in[0];
    const float* Wq = (const float*)d_in[1];
    const float* Wk = (const float*)d_in[2];
    const float* Wv = (const float*)d_in[3];
    const float* Wp = (const float*)d_in[4];
    const float* bp = (const float*)d_in[5];
    float* out = (float*)d_out;

    cudaFuncSetAttribute(gemm_mma_kernel,
                         cudaFuncAttributeMaxDynamicSharedMemorySize, GEMM_SMEM);
    cudaFuncSetAttribute(attn_f16_kernel,
                         cudaFuncAttributeMaxDynamicSharedMemorySize, AT_SMEM);

    transpose_w_kernel<<<1024, 1024>>>(Wq, Wk, Wv, Wp);
    gemm_mma_kernel<<<dim3(128, 4, 3), 256, GEMM_SMEM>>>(x, -1, nullptr, nullptr);
    attn_f16_kernel<<<dim3(Ss / 128, Hh, Bb), 128, AT_SMEM>>>();
    gemm_mma_kernel<<<dim3(128, 4, 1), 256, GEMM_SMEM>>>(x, 3, bp, out);
}

// round 16
// speedup vs baseline: 5.6455x; 1.0221x over previous
#include <cuda_runtime.h>
#include <cuda_fp16.h>
#include <math.h>
#include <cstdint>

#define Bb 8
#define Ss 2048
#define Ee 512
#define Hh 8
#define Dd 64

// Scratch (device globals — no allocations allowed)
__device__ __half g_Qh[Bb*Hh*Ss*Dd];  // [b,h,s,d] fp16, pre-scaled by 0.125*log2e
__device__ __half g_Kh[Bb*Hh*Ss*Dd];  // [b,h,s,d] fp16
__device__ __half g_Vh[Bb*Hh*Dd*Ss];  // [b,h,d,s] fp16 (V transposed)
__device__ float  g_att[Bb*Ss*Ee];    // [b*s, h*d] attention output (fp32)
__device__ float  g_Wt[4*Ee*Ee];      // [proj][n][k] transposed weights (tf32)

#define QSC 0.180336880111120426f     // 0.125 * log2(e)

// ---------------------------------------------------------------------------
__device__ __forceinline__ uint32_t smem_u32(const void* p) {
    uint32_t a;
    asm("{ .reg .u64 t; cvta.to.shared.u64 t, %1; cvt.u32.u64 %0, t; }" : "=r"(a) : "l"(p));
    return a;
}
#define CP_ASYNC16(dst_u32, src_ptr) \
    asm volatile("cp.async.cg.shared.global [%0], [%1], 16;" \
        :: "r"(dst_u32), "l"(__cvta_generic_to_global(src_ptr)) : "memory")
#define CP_COMMIT() asm volatile("cp.async.commit_group;" ::: "memory")
#define CP_WAIT_1() asm volatile("cp.async.wait_group 1;" ::: "memory")

#define MMA_TF32(c, a, b) \
    asm volatile("mma.sync.aligned.m16n8k8.row.col.f32.tf32.tf32.f32 " \
        "{%0,%1,%2,%3}, {%4,%5,%6,%7}, {%8,%9}, {%0,%1,%2,%3};" \
        : "+f"((c)[0]), "+f"((c)[1]), "+f"((c)[2]), "+f"((c)[3]) \
        : "r"((a)[0]), "r"((a)[1]), "r"((a)[2]), "r"((a)[3]), \
          "r"((b)[0]), "r"((b)[1]))

#define MMA_F16(c, a, b) \
    asm volatile("mma.sync.aligned.m16n8k16.row.col.f32.f16.f16.f32 " \
        "{%0,%1,%2,%3}, {%4,%5,%6,%7}, {%8,%9}, {%0,%1,%2,%3};" \
        : "+f"((c)[0]), "+f"((c)[1]), "+f"((c)[2]), "+f"((c)[3]) \
        : "r"((a)[0]), "r"((a)[1]), "r"((a)[2]), "r"((a)[3]), \
          "r"((b)[0]), "r"((b)[1]))

#define LDSM_X4(r0, r1, r2, r3, addr) \
    asm volatile("ldmatrix.sync.aligned.m8n8.x4.shared.b16 {%0,%1,%2,%3}, [%4];" \
        : "=r"(r0), "=r"(r1), "=r"(r2), "=r"(r3) : "r"(addr))

__device__ __forceinline__ uint32_t f2tf32(float f) {
    uint32_t u;
    asm("cvt.rna.tf32.f32 %0, %1;" : "=r"(u) : "f"(f));
    return u;
}
__device__ __forceinline__ float fexp2(float x) {
    float y;
    asm("ex2.approx.ftz.f32 %0, %1;" : "=f"(y) : "f"(x));
    return y;
}
__device__ __forceinline__ uint32_t fbits(float f) { return __float_as_uint(f); }
__device__ __forceinline__ uint32_t pack_h2(float lo, float hi) {
    __half2 h = __floats2half2_rn(lo, hi);
    return *(uint32_t*)&h;
}

// ---------------------------------------------------------------------------
// Weight transpose + tf32 round: g_Wt[p][n][k]
// ---------------------------------------------------------------------------
__global__ __launch_bounds__(1024) void transpose_w_kernel(
    const float* __restrict__ Wq, const float* __restrict__ Wk,
    const float* __restrict__ Wv, const float* __restrict__ Wp)
{
    const int idx = blockIdx.x * 1024 + threadIdx.x;
    const int p = idx >> 18;
    const int r = idx & 262143;
    const int n = r >> 9;
    const int k = r & 511;
    const float* __restrict__ W = (p == 0) ? Wq : (p == 1) ? Wk : (p == 2) ? Wv : Wp;
    float v;
    if (p < 3) {
        const int h = n >> 6, d = n & 63;
        v = W[(h * Ee + k) * Dd + d];
    } else {
        v = W[k * Ee + n];
    }
    g_Wt[idx] = __uint_as_float(f2tf32(v));
}

// ---------------------------------------------------------------------------
// tf32 mma.sync GEMM: C[16384x512] = A * Wt^T.
// mode: 0=Q (fp16, scaled), 1=K (fp16), 2=V^T (fp16), 3=proj (+bias -> out).
// ---------------------------------------------------------------------------
#define STAGE_F (128*32 + 128*32)
#define GEMM_SMEM (2 * STAGE_F * 4)

__global__ __launch_bounds__(256) void gemm_mma_kernel(
    const float* __restrict__ Aglob, int mode_in,
    const float* __restrict__ bp, float* __restrict__ out)
{
    extern __shared__ float sm[];
    const int tid = threadIdx.x;
    const int wid = tid >> 5;
    const int lane = tid & 31;
    const int g = lane >> 2;
    const int t = lane & 3;
    const int wm = wid & 3;
    const int wn = wid >> 2;

    const int mode = (mode_in < 0) ? (int)blockIdx.z : mode_in;
    const float* __restrict__ Ag = (mode == 3) ? g_att : Aglob;
    const float* __restrict__ Bg = g_Wt + (size_t)mode * (Ee * Ee);
    const int m0 = blockIdx.x * 128;
    const int n0 = blockIdx.y * 128;

    const uint32_t smb = smem_u32(sm);

    float c[2][8][4];
#pragma unroll
    for (int i = 0; i < 2; i++)
#pragma unroll
        for (int j = 0; j < 8; j++)
#pragma unroll
            for (int q = 0; q < 4; q++) c[i][j][q] = 0.0f;

    auto load_stage = [&](int kt) {
        const uint32_t base = smb + (uint32_t)(kt & 1) * (STAGE_F * 4);
        const int k0 = kt * 32;
#pragma unroll
        for (int p = 0; p < 4; p++) {
            const int id = tid + p * 256;
            const int row = id >> 3, ch = id & 7;
            CP_ASYNC16(base + (uint32_t)(row * 128 + ((ch ^ (row & 7)) * 16)),
                       Ag + (size_t)(m0 + row) * Ee + k0 + ch * 4);
        }
        const uint32_t bbase = base + 128 * 32 * 4;
#pragma unroll
        for (int p = 0; p < 4; p++) {
            const int id = tid + p * 256;
            const int row = id >> 3, ch = id & 7;
            CP_ASYNC16(bbase + (uint32_t)(row * 128 + ((ch ^ (row & 7)) * 16)),
                       Bg + (size_t)(n0 + row) * Ee + k0 + ch * 4);
        }
    };

    load_stage(0);
    CP_COMMIT();

    const int NT = Ee / 32;
    for (int kt = 0; kt < NT; kt++) {
        if (kt + 1 < NT) load_stage(kt + 1);
        CP_COMMIT();
        CP_WAIT_1();
        __syncthreads();

        const float* As = sm + (kt & 1) * STAGE_F;
        const float* Bs = As + 128 * 32;

#pragma unroll
        for (int ks = 0; ks < 4; ks++) {
            const int ch0 = (2 * ks) ^ g;
            const int ch1 = (2 * ks + 1) ^ g;

            uint32_t a[2][4];
#pragma unroll
            for (int i = 0; i < 2; i++) {
                const int row = wm * 32 + i * 16 + g;
                a[i][0] = f2tf32(As[row * 32 + ch0 * 4 + t]);
                a[i][1] = f2tf32(As[(row + 8) * 32 + ch0 * 4 + t]);
                a[i][2] = f2tf32(As[row * 32 + ch1 * 4 + t]);
                a[i][3] = f2tf32(As[(row + 8) * 32 + ch1 * 4 + t]);
            }
            uint32_t b[8][2];
#pragma unroll
            for (int j = 0; j < 8; j++) {
                const int rn = wn * 64 + j * 8 + g;
                b[j][0] = fbits(Bs[rn * 32 + ch0 * 4 + t]);
                b[j][1] = fbits(Bs[rn * 32 + ch1 * 4 + t]);
            }
#pragma unroll
            for (int i = 0; i < 2; i++)
#pragma unroll
                for (int j = 0; j < 8; j++)
                    MMA_TF32(c[i][j], a[i], b[j]);
        }
        __syncthreads();
    }

    // Epilogue. Fragment (i,j): rows m0+wm*32+i*16+g (+8), cols n0+wn*64+j*8+2t (+1)
#pragma unroll
    for (int i = 0; i < 2; i++) {
        const int mrow = m0 + wm * 32 + i * 16 + g;
#pragma unroll
        for (int rr = 0; rr < 2; rr++) {
            const int m = mrow + rr * 8;
            const int b_ = m >> 11;
            const int s = m & 2047;
#pragma unroll
            for (int j = 0; j < 8; j++) {
                const int n = n0 + wn * 64 + j * 8 + 2 * t;
                const float v0 = c[i][j][rr * 2 + 0];
                const float v1 = c[i][j][rr * 2 + 1];
                const int h = n >> 6, d = n & 63;
                const size_t bh = (size_t)(b_ * Hh + h);
                if (mode == 0) {
                    __half2* dst = (__half2*)(g_Qh + (bh * Ss + s) * Dd + d);
                    *dst = __floats2half2_rn(v0 * QSC, v1 * QSC);
                } else if (mode == 1) {
                    __half2* dst = (__half2*)(g_Kh + (bh * Ss + s) * Dd + d);
                    *dst = __floats2half2_rn(v0, v1);
                } else if (mode == 2) {
                    __half* dst = g_Vh + (bh * Dd + d) * Ss + s;
                    dst[0]  = __float2half_rn(v0);
                    dst[Ss] = __float2half_rn(v1);
                } else {
                    float* dst = out + (size_t)m * Ee + n;
                    *(float2*)dst = make_float2(v0 + bp[n], v1 + bp[n + 1]);
                }
            }
        }
    }
}

// ---------------------------------------------------------------------------
// fp16 flash attention (R14 structure + ldmatrix fragment loads).
// CTA = 4 warps, 128 q-rows; warp w owns rows [w*32, w*32+32) (two 16-row
// A-tiles). m16n8k16 f16 MMAs, fp32 accum, P in registers. SMEM stride 72
// halves; 54 KB -> 2 CTAs/SM. Two syncthreads per tile (known good).
// ---------------------------------------------------------------------------
#define AT_SMEM ((128*72 + 4*64*72) * 2)

__global__ __launch_bounds__(128, 2) void attn_f16_kernel()
{
    extern __shared__ float sm[];
    const int qt = (int)(gridDim.x - 1 - blockIdx.x);   // heavy tiles first
    const int h  = blockIdx.y;
    const int b  = blockIdx.z;
    const int tid = threadIdx.x;
    const int w = tid >> 5;
    const int lane = tid & 31;
    const int g = lane >> 2;
    const int t = lane & 3;
    const int Q0 = qt * 128;
    const int wbase = w * 32;

    const size_t bh = (size_t)(b * Hh + h);
    const __half* __restrict__ Qg = g_Qh + (bh * Ss + Q0) * Dd;
    const __half* __restrict__ Kg = g_Kh + bh * Ss * Dd;
    const __half* __restrict__ Vg = g_Vh + bh * Dd * Ss;

    const uint32_t smb = smem_u32(sm);
    const uint32_t kb0 = smb + 128 * 72 * 2;
    const uint32_t vb0 = kb0 + 2 * 64 * 72 * 2;

    // ldmatrix per-lane address components
    const int l7    = lane & 7;
    const int jsel8 = (lane >> 4) << 3;           // B-frags: row-half select
    const int ksel  = ((lane >> 3) & 1) << 3;     // B-frags: k-half select
    const int qrow  = lane & 15;                  // A-frags: row within 16
    const int qk8   = (lane >> 4) << 3;           // A-frags: k-half select

    // Q tile: 128 rows x 8 chunks (16B = 8 halves), 128 threads -> 8 iters
#pragma unroll
    for (int p = 0; p < 8; p++) {
        const int id = tid + p * 128;
        const int r = id >> 3, ch = id & 7;
        CP_ASYNC16(smb + (uint32_t)(r * 72 + ch * 8) * 2, Qg + r * Dd + ch * 8);
    }
    auto issue_kv = [&](int j) {
        const uint32_t kd = kb0 + (uint32_t)(j & 1) * (64 * 72 * 2);
        const uint32_t vd = vb0 + (uint32_t)(j & 1) * (64 * 72 * 2);
#pragma unroll
        for (int p = 0; p < 4; p++) {
            const int id = tid + p * 128;
            const int r = id >> 3, ch = id & 7;
            CP_ASYNC16(kd + (uint32_t)(r * 72 + ch * 8) * 2,
                       Kg + (size_t)(j * 64 + r) * Dd + ch * 8);
            CP_ASYNC16(vd + (uint32_t)(r * 72 + ch * 8) * 2,
                       Vg + (size_t)r * Ss + j * 64 + ch * 8);
        }
    };
    issue_kv(0);
    CP_COMMIT();

    float o[2][8][4];
#pragma unroll
    for (int it = 0; it < 2; it++)
#pragma unroll
        for (int j = 0; j < 8; j++)
#pragma unroll
            for (int q = 0; q < 4; q++) o[it][j][q] = 0.0f;
    float mr[2][2] = {{-1e30f, -1e30f}, {-1e30f, -1e30f}};
    float lr[2][2] = {{0.0f, 0.0f}, {0.0f, 0.0f}};

    const int jmax = 2 * qt + 1;

    for (int j = 0; j <= jmax; j++) {
        if (j < jmax) issue_kv(j + 1);
        CP_COMMIT();
        CP_WAIT_1();
        __syncthreads();

        if (j * 64 <= Q0 + wbase + 31) {     // warp has unmasked work
            const uint32_t kbase = kb0 + (uint32_t)(j & 1) * (64 * 72 * 2);
            const uint32_t vbase = vb0 + (uint32_t)(j & 1) * (64 * 72 * 2);

            // ---- S = Q K^T: ldmatrix fragments ----
            float c[2][8][4];
#pragma unroll
            for (int it = 0; it < 2; it++)
#pragma unroll
                for (int jn = 0; jn < 8; jn++)
#pragma unroll
                    for (int q = 0; q < 4; q++) c[it][jn][q] = 0.0f;

#pragma unroll
            for (int ks = 0; ks < 4; ks++) {
                uint32_t bb[8][2];
#pragma unroll
                for (int p = 0; p < 4; p++) {
                    const uint32_t ka = kbase +
                        (uint32_t)((16 * p + jsel8 + l7) * 72 + ks * 16 + ksel) * 2;
                    LDSM_X4(bb[2*p][0], bb[2*p][1], bb[2*p+1][0], bb[2*p+1][1], ka);
                }
#pragma unroll
                for (int it = 0; it < 2; it++) {
                    uint32_t a[4];
                    const uint32_t qa = smb +
                        (uint32_t)((wbase + it * 16 + qrow) * 72 + ks * 16 + qk8) * 2;
                    LDSM_X4(a[0], a[1], a[2], a[3], qa);
#pragma unroll
                    for (int jn = 0; jn < 8; jn++)
                        MMA_F16(c[it][jn], a, bb[jn]);
                }
            }

            // ---- causal mask (diagonal region only) ----
            if (j * 64 + 63 > Q0 + wbase) {
                const int cb = j * 64 - Q0;
#pragma unroll
                for (int it = 0; it < 2; it++) {
                    const int ra = wbase + it * 16 + g;
#pragma unroll
                    for (int jn = 0; jn < 8; jn++) {
                        const int c0 = cb + jn * 8 + 2 * t;
                        if (c0     > ra)     c[it][jn][0] = -1e30f;
                        if (c0 + 1 > ra)     c[it][jn][1] = -1e30f;
                        if (c0     > ra + 8) c[it][jn][2] = -1e30f;
                        if (c0 + 1 > ra + 8) c[it][jn][3] = -1e30f;
                    }
                }
            }

            // ---- online softmax (base-2) per A-tile (R14 known-good) ----
#pragma unroll
            for (int it = 0; it < 2; it++) {
                float tm0 = -1e30f, tm1 = -1e30f;
#pragma unroll
                for (int jn = 0; jn < 8; jn++) {
                    tm0 = fmaxf(tm0, fmaxf(c[it][jn][0], c[it][jn][1]));
                    tm1 = fmaxf(tm1, fmaxf(c[it][jn][2], c[it][jn][3]));
                }
                tm0 = fmaxf(tm0, __shfl_xor_sync(0xffffffffu, tm0, 1));
                tm0 = fmaxf(tm0, __shfl_xor_sync(0xffffffffu, tm0, 2));
                tm1 = fmaxf(tm1, __shfl_xor_sync(0xffffffffu, tm1, 1));
                tm1 = fmaxf(tm1, __shfl_xor_sync(0xffffffffu, tm1, 2));

                const float mn0 = fmaxf(mr[it][0], tm0);
                const float mn1 = fmaxf(mr[it][1], tm1);
                const float al0 = fexp2(mr[it][0] - mn0);
                const float al1 = fexp2(mr[it][1] - mn1);
                mr[it][0] = mn0; mr[it][1] = mn1;

                float sum0 = 0.0f, sum1 = 0.0f;
#pragma unroll
                for (int jn = 0; jn < 8; jn++) {
                    c[it][jn][0] = fexp2(c[it][jn][0] - mn0);
                    c[it][jn][1] = fexp2(c[it][jn][1] - mn0);
                    c[it][jn][2] = fexp2(c[it][jn][2] - mn1);
                    c[it][jn][3] = fexp2(c[it][jn][3] - mn1);
                    sum0 += c[it][jn][0] + c[it][jn][1];
                    sum1 += c[it][jn][2] + c[it][jn][3];
                }
                sum0 += __shfl_xor_sync(0xffffffffu, sum0, 1);
                sum0 += __shfl_xor_sync(0xffffffffu, sum0, 2);
                sum1 += __shfl_xor_sync(0xffffffffu, sum1, 1);
                sum1 += __shfl_xor_sync(0xffffffffu, sum1, 2);
                lr[it][0] = lr[it][0] * al0 + sum0;
                lr[it][1] = lr[it][1] * al1 + sum1;

#pragma unroll
                for (int jn = 0; jn < 8; jn++) {
                    o[it][jn][0] *= al0; o[it][jn][1] *= al0;
                    o[it][jn][2] *= al1; o[it][jn][3] *= al1;
                }
            }

            // ---- O += P @ V: ldmatrix V fragments, P packed from registers ----
#pragma unroll
            for (int ks = 0; ks < 4; ks++) {
                uint32_t vv[8][2];
#pragma unroll
                for (int p = 0; p < 4; p++) {
                    const uint32_t va = vbase +
                        (uint32_t)((16 * p + jsel8 + l7) * 72 + ks * 16 + ksel) * 2;
                    LDSM_X4(vv[2*p][0], vv[2*p][1], vv[2*p+1][0], vv[2*p+1][1], va);
                }
#pragma unroll
                for (int it = 0; it < 2; it++) {
                    uint32_t a[4];
                    a[0] = pack_h2(c[it][2 * ks][0],     c[it][2 * ks][1]);
                    a[1] = pack_h2(c[it][2 * ks][2],     c[it][2 * ks][3]);
                    a[2] = pack_h2(c[it][2 * ks + 1][0], c[it][2 * ks + 1][1]);
                    a[3] = pack_h2(c[it][2 * ks + 1][2], c[it][2 * ks + 1][3]);
#pragma unroll
                    for (int jn = 0; jn < 8; jn++)
                        MMA_F16(o[it][jn], a, vv[jn]);
                }
            }
        }
        __syncthreads();
    }

    // ---- epilogue: normalize, write [b*s][h*64+d] ----
#pragma unroll
    for (int it = 0; it < 2; it++) {
        const float i0 = 1.0f / lr[it][0];
        const float i1 = 1.0f / lr[it][1];
        const size_t row0 = ((size_t)b * Ss + Q0 + wbase + it * 16 + g) * Ee + h * 64;
        const size_t row1 = row0 + 8 * Ee;
#pragma unroll
        for (int jn = 0; jn < 8; jn++) {
            const int d = jn * 8 + 2 * t;
            *(float2*)&g_att[row0 + d] =
                make_float2(o[it][jn][0] * i0, o[it][jn][1] * i0);
            *(float2*)&g_att[row1 + d] =
                make_float2(o[it][jn][2] * i1, o[it][jn][3] * i1);
        }
    }
}

// ---------------------------------------------------------------------------
extern "C" void kernel_launch(void* const* d_in, const int* in_sizes, int n_in,
                              void* d_out, int out_size)
{
    (void)in_sizes; (void)n_in; (void)out_size;
    const float* x  = (const float*)d_in[0];
    const float* Wq = (const float*)d_in[1];
    const float* Wk = (const float*)d_in[2];
    const float* Wv = (const float*)d_in[3];
    const float* Wp = (const float*)d_in[4];
    const float* bp = (const float*)d_in[5];
    float* out = (float*)d_out;

    cudaFuncSetAttribute(gemm_mma_kernel,
                         cudaFuncAttributeMaxDynamicSharedMemorySize, GEMM_SMEM);
    cudaFuncSetAttribute(attn_f16_kernel,
                         cudaFuncAttributeMaxDynamicSharedMemorySize, AT_SMEM);

    transpose_w_kernel<<<1024, 1024>>>(Wq, Wk, Wv, Wp);
    gemm_mma_kernel<<<dim3(128, 4, 3), 256, GEMM_SMEM>>>(x, -1, nullptr, nullptr);
    attn_f16_kernel<<<dim3(Ss / 128, Hh, Bb), 128, AT_SMEM>>>();
    gemm_mma_kernel<<<dim3(128, 4, 1), 256, GEMM_SMEM>>>(x, 3, bp, out);
}